// round 3
// baseline (speedup 1.0000x reference)
#include <cuda_runtime.h>
#include <math.h>

#define NNODES 100000
#define NEDGES 150000
#define NPRED  200000
#define DDIM   512

// ---------------- scratch (no allocs allowed) ----------------
__device__ float g_h  [(size_t)NNODES * DDIM];   // GEMM output / layer2 output
__device__ float g_agg[(size_t)NNODES * DDIM];   // aggregation buffer
__device__ float g_x1 [(size_t)NNODES * DDIM];   // layer1 output (residual for layer2)
__device__ float g_deg [NNODES];
__device__ float g_dinv[NNODES];
__device__ float g_enorm[NEDGES];
__device__ float g_p   [NNODES * 2];
__device__ float g_pagg[NNODES * 2];
__device__ float g_ls  [NNODES * 2];

// ---------------- degree / norm precompute ----------------
__global__ void k_deg_init(int n) {
    int i = blockIdx.x * blockDim.x + threadIdx.x;
    if (i < n) g_deg[i] = 1.0f;  // self-loop weight 1
}

__global__ void k_deg_edges(const int* __restrict__ ei,
                            const float* __restrict__ w, int E) {
    int e = blockIdx.x * blockDim.x + threadIdx.x;
    if (e < E) atomicAdd(&g_deg[ei[E + e]], w[e]);  // scatter to col
}

__global__ void k_dinv(int n) {
    int i = blockIdx.x * blockDim.x + threadIdx.x;
    if (i < n) {
        float d = g_deg[i];
        g_dinv[i] = (d > 0.0f) ? rsqrtf(fmaxf(d, 1e-12f)) : 0.0f;
    }
}

__global__ void k_enorm(const int* __restrict__ ei,
                        const float* __restrict__ w, int E) {
    int e = blockIdx.x * blockDim.x + threadIdx.x;
    if (e < E) {
        int r = ei[e], c = ei[E + e];
        g_enorm[e] = g_dinv[r] * w[e] * g_dinv[c];
    }
}

// ---------------- GEMM: C[M,512] = A[M,512] @ B[512,512], fp32 ----------------
// 128x64 block tile, BK=16, 256 threads, 8x4 per-thread micro-tile.
__global__ __launch_bounds__(256) void gemm_512(const float* __restrict__ A,
                                                const float* __restrict__ B,
                                                float* __restrict__ C, int M) {
    __shared__ float As[16][128];
    __shared__ float Bs[16][64];

    const int tid = threadIdx.x;
    const int bm = blockIdx.x * 128;
    const int bn = blockIdx.y * 64;
    const int ty = tid >> 4;          // 0..15 -> M micro rows (x8)
    const int tx = tid & 15;          // 0..15 -> N micro cols (x4)

    const int ar = tid >> 2;          // 0..63 (and +64)
    const int ac = (tid & 3) * 4;     // 0,4,8,12
    const int br = tid >> 4;          // 0..15
    const int bc = (tid & 15) * 4;    // 0..60

    float acc[8][4];
#pragma unroll
    for (int i = 0; i < 8; i++)
#pragma unroll
        for (int j = 0; j < 4; j++) acc[i][j] = 0.0f;

    for (int k0 = 0; k0 < 512; k0 += 16) {
        // load A tile (two 64-row halves), transpose into As[k][m]
        float4 a0 = make_float4(0.f, 0.f, 0.f, 0.f);
        float4 a1 = make_float4(0.f, 0.f, 0.f, 0.f);
        if (bm + ar < M)
            a0 = *(const float4*)&A[(size_t)(bm + ar) * 512 + k0 + ac];
        if (bm + ar + 64 < M)
            a1 = *(const float4*)&A[(size_t)(bm + ar + 64) * 512 + k0 + ac];
        As[ac + 0][ar] = a0.x; As[ac + 1][ar] = a0.y;
        As[ac + 2][ar] = a0.z; As[ac + 3][ar] = a0.w;
        As[ac + 0][ar + 64] = a1.x; As[ac + 1][ar + 64] = a1.y;
        As[ac + 2][ar + 64] = a1.z; As[ac + 3][ar + 64] = a1.w;

        // load B tile
        float4 b = *(const float4*)&B[(size_t)(k0 + br) * 512 + bn + bc];
        *(float4*)&Bs[br][bc] = b;

        __syncthreads();

#pragma unroll
        for (int k = 0; k < 16; k++) {
            float4 av0 = *(const float4*)&As[k][ty * 8];
            float4 av1 = *(const float4*)&As[k][ty * 8 + 4];
            float4 bv  = *(const float4*)&Bs[k][tx * 4];
            float am[8] = {av0.x, av0.y, av0.z, av0.w, av1.x, av1.y, av1.z, av1.w};
            float bm4[4] = {bv.x, bv.y, bv.z, bv.w};
#pragma unroll
            for (int i = 0; i < 8; i++)
#pragma unroll
                for (int j = 0; j < 4; j++) acc[i][j] += am[i] * bm4[j];
        }
        __syncthreads();
    }

#pragma unroll
    for (int i = 0; i < 8; i++) {
        int row = bm + ty * 8 + i;
        if (row < M)
            *(float4*)&C[(size_t)row * 512 + bn + tx * 4] =
                make_float4(acc[i][0], acc[i][1], acc[i][2], acc[i][3]);
    }
}

// ---------------- aggregation ----------------
// agg[i] = dinv[i]^2 * h[i]   (self-loop term), vectorized
__global__ void k_agg_init(const float4* __restrict__ h, float4* __restrict__ agg,
                           int total4) {
    int i = blockIdx.x * blockDim.x + threadIdx.x;
    if (i >= total4) return;
    int node = i >> 7;                 // 128 float4 per node (512 floats)
    float s = g_dinv[node]; s = s * s;
    float4 v = h[i];
    v.x *= s; v.y *= s; v.z *= s; v.w *= s;
    agg[i] = v;
}

// one warp per edge: agg[col] += enorm * h[row]
__global__ void k_scatter(const float* __restrict__ h, float* __restrict__ agg,
                          const int* __restrict__ ei, int E) {
    int e = blockIdx.x * (blockDim.x >> 5) + (threadIdx.x >> 5);
    if (e >= E) return;
    int lane = threadIdx.x & 31;
    int r = ei[e], c = ei[E + e];
    float nm = g_enorm[e];
    const float* hr = h + (size_t)r * 512;
    float* ac = agg + (size_t)c * 512;
#pragma unroll
    for (int j = 0; j < 16; j++)
        atomicAdd(ac + lane + j * 32, nm * hr[lane + j * 32]);
}

// ---------------- epilogue: relu -> row L2 normalize -> residual avg ----------
// one block (128 threads) per node; out = (relu(agg+b)/nrm + resid)*0.5
__global__ __launch_bounds__(128) void k_epilogue(const float* __restrict__ agg,
                                                  const float* __restrict__ bias,
                                                  const float* __restrict__ resid,
                                                  float* __restrict__ out, int n) {
    int node = blockIdx.x;
    if (node >= n) return;
    int tid = threadIdx.x;
    const float4* ag = (const float4*)(agg + (size_t)node * 512);
    const float4* rs = (const float4*)(resid + (size_t)node * 512);
    const float4* bi = (const float4*)bias;
    float4* ot = (float4*)(out + (size_t)node * 512);

    float4 v = ag[tid];
    float4 b = bi[tid];
    v.x = fmaxf(v.x + b.x, 0.0f);
    v.y = fmaxf(v.y + b.y, 0.0f);
    v.z = fmaxf(v.z + b.z, 0.0f);
    v.w = fmaxf(v.w + b.w, 0.0f);

    float s = v.x * v.x + v.y * v.y + v.z * v.z + v.w * v.w;
#pragma unroll
    for (int off = 16; off > 0; off >>= 1)
        s += __shfl_down_sync(0xFFFFFFFFu, s, off);

    __shared__ float warp_s[4];
    __shared__ float s_total;
    if ((tid & 31) == 0) warp_s[tid >> 5] = s;
    __syncthreads();
    if (tid == 0) s_total = warp_s[0] + warp_s[1] + warp_s[2] + warp_s[3];
    __syncthreads();

    float inv = 0.5f / fmaxf(sqrtf(s_total), 1e-12f);
    float4 r = rs[tid];
    ot[tid] = make_float4(v.x * inv + r.x * 0.5f,
                          v.y * inv + r.y * 0.5f,
                          v.z * inv + r.z * 0.5f,
                          v.w * inv + r.w * 0.5f);
}

// ---------------- final projection: p[i,0:2] = h[i,:] @ Wf ----------------
__global__ __launch_bounds__(256) void k_pdot(const float* __restrict__ h,
                                              const float* __restrict__ Wf, int n) {
    __shared__ float sWf[1024];
    int tid = threadIdx.x;
#pragma unroll
    for (int i = tid; i < 1024; i += 256) sWf[i] = Wf[i];
    __syncthreads();

    int node = blockIdx.x * 8 + (tid >> 5);
    if (node >= n) return;
    int lane = tid & 31;
    const float* hr = h + (size_t)node * 512;
    float s0 = 0.f, s1 = 0.f;
#pragma unroll
    for (int j = 0; j < 16; j++) {
        int k = lane + j * 32;
        float hv = hr[k];
        s0 += hv * sWf[k * 2];
        s1 += hv * sWf[k * 2 + 1];
    }
#pragma unroll
    for (int off = 16; off > 0; off >>= 1) {
        s0 += __shfl_down_sync(0xFFFFFFFFu, s0, off);
        s1 += __shfl_down_sync(0xFFFFFFFFu, s1, off);
    }
    if (lane == 0) {
        g_p[node * 2]     = s0;
        g_p[node * 2 + 1] = s1;
    }
}

__global__ void k_pagg_init(int n) {
    int i = blockIdx.x * blockDim.x + threadIdx.x;
    if (i >= n) return;
    float s = g_dinv[i]; s = s * s;
    g_pagg[i * 2]     = s * g_p[i * 2];
    g_pagg[i * 2 + 1] = s * g_p[i * 2 + 1];
}

__global__ void k_pscatter(const int* __restrict__ ei, int E) {
    int e = blockIdx.x * blockDim.x + threadIdx.x;
    if (e >= E) return;
    int r = ei[e], c = ei[E + e];
    float nm = g_enorm[e];
    atomicAdd(&g_pagg[c * 2],     nm * g_p[r * 2]);
    atomicAdd(&g_pagg[c * 2 + 1], nm * g_p[r * 2 + 1]);
}

__global__ void k_lsm(const float* __restrict__ bf, int n) {
    int i = blockIdx.x * blockDim.x + threadIdx.x;
    if (i >= n) return;
    float z0 = g_pagg[i * 2] + bf[0];
    float z1 = g_pagg[i * 2 + 1] + bf[1];
    float m = fmaxf(z0, z1);
    float lse = m + logf(expf(z0 - m) + expf(z1 - m));
    g_ls[i * 2]     = z0 - lse;
    g_ls[i * 2 + 1] = z1 - lse;
}

__global__ void k_pred(const int* __restrict__ pe, float* __restrict__ out,
                       int NP) {
    int p = blockIdx.x * blockDim.x + threadIdx.x;
    if (p >= NP) return;
    int u = pe[p], v = pe[NP + p];
    out[p * 2]     = -(g_ls[u * 2]     * g_ls[v * 2]);
    out[p * 2 + 1] = -(g_ls[u * 2 + 1] * g_ls[v * 2 + 1]);
}

// ---------------- launch ----------------
extern "C" void kernel_launch(void* const* d_in, const int* in_sizes, int n_in,
                              void* d_out, int out_size) {
    const float* x   = (const float*)d_in[0];
    const int*   ei  = (const int*)d_in[1];
    const float* w   = (const float*)d_in[2];
    const int*   pe  = (const int*)d_in[3];
    const float* W1  = (const float*)d_in[4];
    const float* b1  = (const float*)d_in[5];
    const float* W2  = (const float*)d_in[6];
    const float* b2  = (const float*)d_in[7];
    const float* Wf  = (const float*)d_in[8];
    const float* bf  = (const float*)d_in[9];
    float* out = (float*)d_out;

    const int N  = in_sizes[0] / DDIM;     // 100000
    const int E  = in_sizes[2];            // 150000
    const int NP = in_sizes[3] / 2;        // 200000

    float *hbuf, *aggbuf, *x1buf;
    cudaGetSymbolAddress((void**)&hbuf,   g_h);
    cudaGetSymbolAddress((void**)&aggbuf, g_agg);
    cudaGetSymbolAddress((void**)&x1buf,  g_x1);

    const int total4 = N * (DDIM / 4);
    dim3 ggrid((N + 127) / 128, DDIM / 64);

    // degree / norm precompute
    k_deg_init <<<(N + 255) / 256, 256>>>(N);
    k_deg_edges<<<(E + 255) / 256, 256>>>(ei, w, E);
    k_dinv     <<<(N + 255) / 256, 256>>>(N);
    k_enorm    <<<(E + 255) / 256, 256>>>(ei, w, E);

    // ---- layer 1 ----
    gemm_512  <<<ggrid, 256>>>(x, W1, hbuf, N);
    k_agg_init<<<(total4 + 255) / 256, 256>>>((const float4*)hbuf, (float4*)aggbuf, total4);
    k_scatter <<<(E + 7) / 8, 256>>>(hbuf, aggbuf, ei, E);
    k_epilogue<<<N, 128>>>(aggbuf, b1, x, x1buf, N);

    // ---- layer 2 ----
    gemm_512  <<<ggrid, 256>>>(x1buf, W2, hbuf, N);
    k_agg_init<<<(total4 + 255) / 256, 256>>>((const float4*)hbuf, (float4*)aggbuf, total4);
    k_scatter <<<(E + 7) / 8, 256>>>(hbuf, aggbuf, ei, E);
    k_epilogue<<<N, 128>>>(aggbuf, b2, x1buf, hbuf, N);   // layer2 out -> hbuf

    // ---- final conv (512 -> 2) + log_softmax ----
    k_pdot     <<<(N + 7) / 8, 256>>>(hbuf, Wf, N);
    k_pagg_init<<<(N + 255) / 256, 256>>>(N);
    k_pscatter <<<(E + 255) / 256, 256>>>(ei, E);
    k_lsm      <<<(N + 255) / 256, 256>>>(bf, N);

    // ---- predictor edges ----
    k_pred<<<(NP + 255) / 256, 256>>>(pe, out, NP);
}

// round 5
// speedup vs baseline: 1.2062x; 1.2062x over previous
#include <cuda_runtime.h>
#include <cuda_bf16.h>
#include <math.h>
#include <stdint.h>

#define NNODES 100000
#define NEDGES 150000
#define NPRED  200000
#define DDIM   512

// ---------------- scratch (no allocs allowed) ----------------
__device__ float g_h  [(size_t)NNODES * DDIM];
__device__ float g_agg[(size_t)NNODES * DDIM];
__device__ float g_x1 [(size_t)NNODES * DDIM];
__device__ __nv_bfloat16 g_Ahi[(size_t)NNODES * DDIM];
__device__ __nv_bfloat16 g_Alo[(size_t)NNODES * DDIM];
__device__ __nv_bfloat16 g_W1h[512 * 512];
__device__ __nv_bfloat16 g_W1l[512 * 512];
__device__ __nv_bfloat16 g_W2h[512 * 512];
__device__ __nv_bfloat16 g_W2l[512 * 512];
__device__ float g_deg [NNODES];
__device__ float g_dinv[NNODES];
__device__ float g_enorm[NEDGES];
__device__ float g_p   [NNODES * 2];
__device__ float g_pagg[NNODES * 2];
__device__ float g_ls  [NNODES * 2];

// ---------------- helpers ----------------
__device__ __forceinline__ uint32_t smem_u32(const void* p) {
    uint32_t a;
    asm("{ .reg .u64 t; cvta.to.shared.u64 t, %1; cvt.u32.u64 %0, t; }" : "=r"(a) : "l"(p));
    return a;
}
__device__ __forceinline__ uint32_t pack2(__nv_bfloat16 a, __nv_bfloat16 b) {
    return (uint32_t)__bfloat16_as_ushort(a) | ((uint32_t)__bfloat16_as_ushort(b) << 16);
}
__device__ __forceinline__ void cp16(uint32_t dst, const void* src, bool p) {
    asm volatile("cp.async.cg.shared.global [%0], [%1], 16, %2;"
                 :: "r"(dst), "l"(src), "r"(p ? 16 : 0) : "memory");
}
#define CP_COMMIT() asm volatile("cp.async.commit_group;" ::: "memory")
#define CP_WAIT1()  asm volatile("cp.async.wait_group 1;" ::: "memory")
#define CP_WAIT0()  asm volatile("cp.async.wait_group 0;" ::: "memory")
#define LDSM_X4(r, a) asm volatile( \
    "ldmatrix.sync.aligned.m8n8.x4.shared.b16 {%0,%1,%2,%3}, [%4];" \
    : "=r"((r)[0]), "=r"((r)[1]), "=r"((r)[2]), "=r"((r)[3]) : "r"(a))
#define LDSM_X2(r, a) asm volatile( \
    "ldmatrix.sync.aligned.m8n8.x2.shared.b16 {%0,%1}, [%2];" \
    : "=r"((r)[0]), "=r"((r)[1]) : "r"(a))

__device__ __forceinline__ void mma_bf16(float* c, const uint32_t* a, const uint32_t* b) {
    asm volatile(
        "mma.sync.aligned.m16n8k16.row.col.f32.bf16.bf16.f32 "
        "{%0,%1,%2,%3}, {%4,%5,%6,%7}, {%8,%9}, {%0,%1,%2,%3};"
        : "+f"(c[0]), "+f"(c[1]), "+f"(c[2]), "+f"(c[3])
        : "r"(a[0]), "r"(a[1]), "r"(a[2]), "r"(a[3]), "r"(b[0]), "r"(b[1]));
}

// ---------------- degree / norm precompute ----------------
__global__ void k_deg_init(int n) {
    int i = blockIdx.x * blockDim.x + threadIdx.x;
    if (i < n) g_deg[i] = 1.0f;
}
__global__ void k_deg_edges(const int* __restrict__ ei, const float* __restrict__ w, int E) {
    int e = blockIdx.x * blockDim.x + threadIdx.x;
    if (e < E) atomicAdd(&g_deg[ei[E + e]], w[e]);
}
__global__ void k_dinv(int n) {
    int i = blockIdx.x * blockDim.x + threadIdx.x;
    if (i < n) {
        float d = g_deg[i];
        g_dinv[i] = (d > 0.0f) ? rsqrtf(fmaxf(d, 1e-12f)) : 0.0f;
    }
}
__global__ void k_enorm(const int* __restrict__ ei, const float* __restrict__ w, int E) {
    int e = blockIdx.x * blockDim.x + threadIdx.x;
    if (e < E) g_enorm[e] = g_dinv[ei[e]] * w[e] * g_dinv[ei[E + e]];
}

// ---------------- weight transpose + bf16 split: Wt[n][k] ----------------
__global__ void k_wprep(const float* __restrict__ W, __nv_bfloat16* __restrict__ Hi,
                        __nv_bfloat16* __restrict__ Lo) {
    int i = blockIdx.x * blockDim.x + threadIdx.x;
    if (i >= 512 * 512) return;
    int k = i >> 9, n = i & 511;
    float x = W[i];
    __nv_bfloat16 h = __float2bfloat16(x);
    __nv_bfloat16 l = __float2bfloat16(x - __bfloat162float(h));
    Hi[n * 512 + k] = h;
    Lo[n * 512 + k] = l;
}

// ---------------- activation bf16 split ----------------
__global__ void k_asplit(const float4* __restrict__ X, __nv_bfloat16* __restrict__ Hi,
                         __nv_bfloat16* __restrict__ Lo, int n4) {
    int i = blockIdx.x * blockDim.x + threadIdx.x;
    if (i >= n4) return;
    float4 v = X[i];
    __nv_bfloat16 h0 = __float2bfloat16(v.x), h1 = __float2bfloat16(v.y);
    __nv_bfloat16 h2 = __float2bfloat16(v.z), h3 = __float2bfloat16(v.w);
    __nv_bfloat16 l0 = __float2bfloat16(v.x - __bfloat162float(h0));
    __nv_bfloat16 l1 = __float2bfloat16(v.y - __bfloat162float(h1));
    __nv_bfloat16 l2 = __float2bfloat16(v.z - __bfloat162float(h2));
    __nv_bfloat16 l3 = __float2bfloat16(v.w - __bfloat162float(h3));
    ((uint2*)Hi)[i] = make_uint2(pack2(h0, h1), pack2(h2, h3));
    ((uint2*)Lo)[i] = make_uint2(pack2(l0, l1), pack2(l2, l3));
}

// ---------------- mma.sync bf16-3x GEMM ----------------
// C[M,512] = A[M,512] @ W ; B operand = Wt[n][k] pre-split bf16.
// CTA tile 128x256x32, 256 thr / 8 warps (2x4), warp tile 64x64.
// SMEM rows padded to 80B (conflict-free ldmatrix). Double-buffered cp.async.
#define A_HI 0
#define A_LO 10240
#define B_HI 20480
#define B_LO 40960
#define STAGE 61440
#define GEMM_SMEM (2 * STAGE)

__global__ __launch_bounds__(256, 1) void gemm_tc(
    const __nv_bfloat16* __restrict__ Ahi, const __nv_bfloat16* __restrict__ Alo,
    const __nv_bfloat16* __restrict__ Bhi, const __nv_bfloat16* __restrict__ Blo,
    float* __restrict__ hOut, float* __restrict__ aggOut, int M) {
    extern __shared__ char smem[];
    const uint32_t sb = smem_u32(smem);
    const int tid = threadIdx.x, lane = tid & 31, wid = tid >> 5;
    const int bm = blockIdx.x * 128, bn = blockIdx.y * 256;

    // staging roles: A rows ar, ar+64 (chunk ac); B row = tid (4 chunks)
    const int ar = tid >> 2, ac = tid & 3;
    const bool v0 = (bm + ar) < M, v1 = (bm + ar + 64) < M;
    const char* pAh0 = (const char*)Ahi + ((size_t)(bm + ar) * 512 + ac * 8) * 2;
    const char* pAh1 = (const char*)Ahi + ((size_t)(bm + ar + 64) * 512 + ac * 8) * 2;
    const char* pAl0 = (const char*)Alo + ((size_t)(bm + ar) * 512 + ac * 8) * 2;
    const char* pAl1 = (const char*)Alo + ((size_t)(bm + ar + 64) * 512 + ac * 8) * 2;
    const char* pBh  = (const char*)Bhi + ((size_t)(bn + tid) * 512) * 2;
    const char* pBl  = (const char*)Blo + ((size_t)(bn + tid) * 512) * 2;

    auto do_stage = [&](int s, int buf) {
        const uint32_t bo = sb + buf * STAGE;
        const size_t ko = (size_t)s * 64;   // bytes (32 bf16)
        cp16(bo + A_HI + ar * 80 + ac * 16,        pAh0 + ko, v0);
        cp16(bo + A_HI + (ar + 64) * 80 + ac * 16, pAh1 + ko, v1);
        cp16(bo + A_LO + ar * 80 + ac * 16,        pAl0 + ko, v0);
        cp16(bo + A_LO + (ar + 64) * 80 + ac * 16, pAl1 + ko, v1);
#pragma unroll
        for (int c = 0; c < 4; ++c) {
            cp16(bo + B_HI + tid * 80 + c * 16, pBh + ko + c * 16, true);
            cp16(bo + B_LO + tid * 80 + c * 16, pBl + ko + c * 16, true);
        }
        CP_COMMIT();
    };

    const int wm = (wid >> 2) * 64;   // 0 / 64
    const int wn = (wid & 3) * 64;    // 0..192

    float acc[4][8][4];
#pragma unroll
    for (int i = 0; i < 4; i++)
#pragma unroll
        for (int j = 0; j < 8; j++)
#pragma unroll
            for (int k = 0; k < 4; k++) acc[i][j][k] = 0.0f;

    do_stage(0, 0);

    for (int s = 0; s < 16; ++s) {
        if (s + 1 < 16) do_stage(s + 1, (s + 1) & 1);
        if (s + 1 < 16) CP_WAIT1(); else CP_WAIT0();
        __syncthreads();

        const uint32_t bufb = sb + (s & 1) * STAGE;
#pragma unroll
        for (int kk = 0; kk < 2; ++kk) {
            const int k16 = kk * 16;
            uint32_t ah[4][4], al[4][4];
#pragma unroll
            for (int ma = 0; ma < 4; ++ma) {
                uint32_t aaddr = bufb + A_HI +
                    (uint32_t)(wm + ma * 16 + (lane & 15)) * 80 +
                    (uint32_t)(k16 + ((lane >> 4) << 3)) * 2;
                LDSM_X4(ah[ma], aaddr);
                LDSM_X4(al[ma], aaddr + (A_LO - A_HI));
            }
#pragma unroll
            for (int na = 0; na < 8; ++na) {
                uint32_t baddr = bufb + B_HI +
                    (uint32_t)(wn + na * 8 + (lane & 7)) * 80 +
                    (uint32_t)(k16 + (((lane >> 3) & 1) << 3)) * 2;
                uint32_t bh[2], bl[2];
                LDSM_X2(bh, baddr);
                LDSM_X2(bl, baddr + (B_LO - B_HI));
#pragma unroll
                for (int ma = 0; ma < 4; ++ma) {
                    mma_bf16(acc[ma][na], ah[ma], bh);
                    mma_bf16(acc[ma][na], al[ma], bh);
                    mma_bf16(acc[ma][na], ah[ma], bl);
                }
            }
        }
        __syncthreads();
    }

    // epilogue: write h and agg = dinv^2 * h
#pragma unroll
    for (int ma = 0; ma < 4; ++ma) {
        int r0 = bm + wm + ma * 16 + (lane >> 2);
        int r1 = r0 + 8;
        float d0 = 0.f, d1 = 0.f;
        if (r0 < M) { float t = g_dinv[r0]; d0 = t * t; }
        if (r1 < M) { float t = g_dinv[r1]; d1 = t * t; }
#pragma unroll
        for (int na = 0; na < 8; ++na) {
            int col = bn + wn + na * 8 + 2 * (lane & 3);
            float* c = acc[ma][na];
            if (r0 < M) {
                size_t o = (size_t)r0 * 512 + col;
                *(float2*)&hOut[o]   = make_float2(c[0], c[1]);
                *(float2*)&aggOut[o] = make_float2(c[0] * d0, c[1] * d0);
            }
            if (r1 < M) {
                size_t o = (size_t)r1 * 512 + col;
                *(float2*)&hOut[o]   = make_float2(c[2], c[3]);
                *(float2*)&aggOut[o] = make_float2(c[2] * d1, c[3] * d1);
            }
        }
    }
}

// ---------------- edge scatter: agg[col] += enorm * h[row] ----------------
__global__ void k_scatter(const float* __restrict__ h, float* __restrict__ agg,
                          const int* __restrict__ ei, int E) {
    int e = blockIdx.x * (blockDim.x >> 5) + (threadIdx.x >> 5);
    if (e >= E) return;
    int lane = threadIdx.x & 31;
    int r = ei[e], c = ei[E + e];
    float nm = g_enorm[e];
    const float* hr = h + (size_t)r * 512;
    float* ac = agg + (size_t)c * 512;
#pragma unroll
    for (int j = 0; j < 16; j++)
        atomicAdd(ac + lane + j * 32, nm * hr[lane + j * 32]);
}

// ---------------- epilogue: relu -> L2 norm -> residual avg (+ opt bf16 split)
__global__ __launch_bounds__(128) void k_epilogue(const float* __restrict__ agg,
                                                  const float* __restrict__ bias,
                                                  const float* __restrict__ resid,
                                                  float* __restrict__ out,
                                                  __nv_bfloat16* __restrict__ hi,
                                                  __nv_bfloat16* __restrict__ lo,
                                                  int n) {
    int node = blockIdx.x;
    if (node >= n) return;
    int tid = threadIdx.x;
    const float4* ag = (const float4*)(agg + (size_t)node * 512);
    const float4* rs = (const float4*)(resid + (size_t)node * 512);
    const float4* bi = (const float4*)bias;
    float4* ot = (float4*)(out + (size_t)node * 512);

    float4 v = ag[tid];
    float4 b = bi[tid];
    v.x = fmaxf(v.x + b.x, 0.0f);
    v.y = fmaxf(v.y + b.y, 0.0f);
    v.z = fmaxf(v.z + b.z, 0.0f);
    v.w = fmaxf(v.w + b.w, 0.0f);

    float s = v.x * v.x + v.y * v.y + v.z * v.z + v.w * v.w;
#pragma unroll
    for (int off = 16; off > 0; off >>= 1)
        s += __shfl_down_sync(0xFFFFFFFFu, s, off);

    __shared__ float warp_s[4];
    __shared__ float s_total;
    if ((tid & 31) == 0) warp_s[tid >> 5] = s;
    __syncthreads();
    if (tid == 0) s_total = warp_s[0] + warp_s[1] + warp_s[2] + warp_s[3];
    __syncthreads();

    float inv = 0.5f / fmaxf(sqrtf(s_total), 1e-12f);
    float4 r = rs[tid];
    float4 o = make_float4(v.x * inv + r.x * 0.5f, v.y * inv + r.y * 0.5f,
                           v.z * inv + r.z * 0.5f, v.w * inv + r.w * 0.5f);
    ot[tid] = o;
    if (hi) {
        __nv_bfloat16 h0 = __float2bfloat16(o.x), h1 = __float2bfloat16(o.y);
        __nv_bfloat16 h2 = __float2bfloat16(o.z), h3 = __float2bfloat16(o.w);
        __nv_bfloat16 l0 = __float2bfloat16(o.x - __bfloat162float(h0));
        __nv_bfloat16 l1 = __float2bfloat16(o.y - __bfloat162float(h1));
        __nv_bfloat16 l2 = __float2bfloat16(o.z - __bfloat162float(h2));
        __nv_bfloat16 l3 = __float2bfloat16(o.w - __bfloat162float(h3));
        size_t idx = (size_t)node * 128 + tid;   // uint2 units (4 bf16)
        ((uint2*)hi)[idx] = make_uint2(pack2(h0, h1), pack2(h2, h3));
        ((uint2*)lo)[idx] = make_uint2(pack2(l0, l1), pack2(l2, l3));
    }
}

// ---------------- final projection: p[i,0:2] = h[i,:] @ Wf ----------------
__global__ __launch_bounds__(256) void k_pdot(const float* __restrict__ h,
                                              const float* __restrict__ Wf, int n) {
    __shared__ float sWf[1024];
    int tid = threadIdx.x;
#pragma unroll
    for (int i = tid; i < 1024; i += 256) sWf[i] = Wf[i];
    __syncthreads();

    int node = blockIdx.x * 8 + (tid >> 5);
    if (node >= n) return;
    int lane = tid & 31;
    const float* hr = h + (size_t)node * 512;
    float s0 = 0.f, s1 = 0.f;
#pragma unroll
    for (int j = 0; j < 16; j++) {
        int k = lane + j * 32;
        float hv = hr[k];
        s0 += hv * sWf[k * 2];
        s1 += hv * sWf[k * 2 + 1];
    }
#pragma unroll
    for (int off = 16; off > 0; off >>= 1) {
        s0 += __shfl_down_sync(0xFFFFFFFFu, s0, off);
        s1 += __shfl_down_sync(0xFFFFFFFFu, s1, off);
    }
    if (lane == 0) {
        g_p[node * 2]     = s0;
        g_p[node * 2 + 1] = s1;
    }
}

__global__ void k_pagg_init(int n) {
    int i = blockIdx.x * blockDim.x + threadIdx.x;
    if (i >= n) return;
    float s = g_dinv[i]; s = s * s;
    g_pagg[i * 2]     = s * g_p[i * 2];
    g_pagg[i * 2 + 1] = s * g_p[i * 2 + 1];
}

__global__ void k_pscatter(const int* __restrict__ ei, int E) {
    int e = blockIdx.x * blockDim.x + threadIdx.x;
    if (e >= E) return;
    int r = ei[e], c = ei[E + e];
    float nm = g_enorm[e];
    atomicAdd(&g_pagg[c * 2],     nm * g_p[r * 2]);
    atomicAdd(&g_pagg[c * 2 + 1], nm * g_p[r * 2 + 1]);
}

__global__ void k_lsm(const float* __restrict__ bf, int n) {
    int i = blockIdx.x * blockDim.x + threadIdx.x;
    if (i >= n) return;
    float z0 = g_pagg[i * 2] + bf[0];
    float z1 = g_pagg[i * 2 + 1] + bf[1];
    float m = fmaxf(z0, z1);
    float lse = m + logf(expf(z0 - m) + expf(z1 - m));
    g_ls[i * 2]     = z0 - lse;
    g_ls[i * 2 + 1] = z1 - lse;
}

__global__ void k_pred(const int* __restrict__ pe, float* __restrict__ out, int NP) {
    int p = blockIdx.x * blockDim.x + threadIdx.x;
    if (p >= NP) return;
    int u = pe[p], v = pe[NP + p];
    out[p * 2]     = -(g_ls[u * 2]     * g_ls[v * 2]);
    out[p * 2 + 1] = -(g_ls[u * 2 + 1] * g_ls[v * 2 + 1]);
}

// ---------------- launch ----------------
extern "C" void kernel_launch(void* const* d_in, const int* in_sizes, int n_in,
                              void* d_out, int out_size) {
    const float* x   = (const float*)d_in[0];
    const int*   ei  = (const int*)d_in[1];
    const float* w   = (const float*)d_in[2];
    const int*   pe  = (const int*)d_in[3];
    const float* W1  = (const float*)d_in[4];
    const float* b1  = (const float*)d_in[5];
    const float* W2  = (const float*)d_in[6];
    const float* b2  = (const float*)d_in[7];
    const float* Wf  = (const float*)d_in[8];
    const float* bf  = (const float*)d_in[9];
    float* out = (float*)d_out;

    const int N  = in_sizes[0] / DDIM;
    const int E  = in_sizes[2];
    const int NP = in_sizes[3] / 2;

    float *hbuf, *aggbuf, *x1buf;
    __nv_bfloat16 *ahi, *alo, *w1h, *w1l, *w2h, *w2l;
    cudaGetSymbolAddress((void**)&hbuf,   g_h);
    cudaGetSymbolAddress((void**)&aggbuf, g_agg);
    cudaGetSymbolAddress((void**)&x1buf,  g_x1);
    cudaGetSymbolAddress((void**)&ahi, g_Ahi);
    cudaGetSymbolAddress((void**)&alo, g_Alo);
    cudaGetSymbolAddress((void**)&w1h, g_W1h);
    cudaGetSymbolAddress((void**)&w1l, g_W1l);
    cudaGetSymbolAddress((void**)&w2h, g_W2h);
    cudaGetSymbolAddress((void**)&w2l, g_W2l);

    cudaFuncSetAttribute(gemm_tc, cudaFuncAttributeMaxDynamicSharedMemorySize,
                         GEMM_SMEM);

    dim3 ggrid((N + 127) / 128, 2);
    const int n4 = N * (DDIM / 4);

    // precompute
    k_deg_init <<<(N + 255) / 256, 256>>>(N);
    k_deg_edges<<<(E + 255) / 256, 256>>>(ei, w, E);
    k_dinv     <<<(N + 255) / 256, 256>>>(N);
    k_enorm    <<<(E + 255) / 256, 256>>>(ei, w, E);
    k_wprep    <<<(512 * 512 + 255) / 256, 256>>>(W1, w1h, w1l);
    k_wprep    <<<(512 * 512 + 255) / 256, 256>>>(W2, w2h, w2l);
    k_asplit   <<<(n4 + 255) / 256, 256>>>((const float4*)x, ahi, alo, n4);

    // ---- layer 1 ----
    gemm_tc   <<<ggrid, 256, GEMM_SMEM>>>(ahi, alo, w1h, w1l, hbuf, aggbuf, N);
    k_scatter <<<(E + 7) / 8, 256>>>(hbuf, aggbuf, ei, E);
    k_epilogue<<<N, 128>>>(aggbuf, b1, x, x1buf, ahi, alo, N);   // fused split for L2

    // ---- layer 2 ----
    gemm_tc   <<<ggrid, 256, GEMM_SMEM>>>(ahi, alo, w2h, w2l, hbuf, aggbuf, N);
    k_scatter <<<(E + 7) / 8, 256>>>(hbuf, aggbuf, ei, E);
    k_epilogue<<<N, 128>>>(aggbuf, b2, x1buf, hbuf, (\
__nv_bfloat16*)0, (__nv_bfloat16*)0, N);

    // ---- final conv (512 -> 2) + log_softmax ----
    k_pdot     <<<(N + 7) / 8, 256>>>(hbuf, Wf, N);
    k_pagg_init<<<(N + 255) / 256, 256>>>(N);
    k_pscatter <<<(E + 255) / 256, 256>>>(ei, E);
    k_lsm      <<<(N + 255) / 256, 256>>>(bf, N);

    // ---- predictor edges ----
    k_pred<<<(NP + 255) / 256, 256>>>(pe, out, NP);
}

// round 6
// speedup vs baseline: 1.2979x; 1.0760x over previous
#include <cuda_runtime.h>
#include <cuda_bf16.h>
#include <math.h>
#include <stdint.h>

#define NNODES 100000
#define NEDGES 150000
#define NPRED  200000
#define DDIM   512

// ---------------- scratch (no allocs allowed) ----------------
__device__ float g_h  [(size_t)NNODES * DDIM];
__device__ float g_agg[(size_t)NNODES * DDIM];
__device__ float g_x1 [(size_t)NNODES * DDIM];
__device__ __nv_bfloat16 g_Ahi[(size_t)NNODES * DDIM];
__device__ __nv_bfloat16 g_Alo[(size_t)NNODES * DDIM];
__device__ __nv_bfloat16 g_W1h[512 * 512];
__device__ __nv_bfloat16 g_W1l[512 * 512];
__device__ __nv_bfloat16 g_W2h[512 * 512];
__device__ __nv_bfloat16 g_W2l[512 * 512];
__device__ float g_deg [NNODES];
__device__ float g_dinv[NNODES];
__device__ float g_enorm[NEDGES];
__device__ float g_p   [NNODES * 2];
__device__ float g_pagg[NNODES * 2];
__device__ float g_ls  [NNODES * 2];

// ---------------- helpers ----------------
__device__ __forceinline__ uint32_t smem_u32(const void* p) {
    uint32_t a;
    asm("{ .reg .u64 t; cvta.to.shared.u64 t, %1; cvt.u32.u64 %0, t; }" : "=r"(a) : "l"(p));
    return a;
}
__device__ __forceinline__ uint32_t pack2(__nv_bfloat16 a, __nv_bfloat16 b) {
    return (uint32_t)__bfloat16_as_ushort(a) | ((uint32_t)__bfloat16_as_ushort(b) << 16);
}
__device__ __forceinline__ void cp16(uint32_t dst, const void* src, bool p) {
    asm volatile("cp.async.cg.shared.global [%0], [%1], 16, %2;"
                 :: "r"(dst), "l"(src), "r"(p ? 16 : 0) : "memory");
}
#define CP_COMMIT() asm volatile("cp.async.commit_group;" ::: "memory")
#define CP_WAIT1()  asm volatile("cp.async.wait_group 1;" ::: "memory")
#define CP_WAIT0()  asm volatile("cp.async.wait_group 0;" ::: "memory")
#define LDSM_X4(r, a) asm volatile( \
    "ldmatrix.sync.aligned.m8n8.x4.shared.b16 {%0,%1,%2,%3}, [%4];" \
    : "=r"((r)[0]), "=r"((r)[1]), "=r"((r)[2]), "=r"((r)[3]) : "r"(a))
#define LDSM_X2(r, a) asm volatile( \
    "ldmatrix.sync.aligned.m8n8.x2.shared.b16 {%0,%1}, [%2];" \
    : "=r"((r)[0]), "=r"((r)[1]) : "r"(a))

__device__ __forceinline__ void mma_bf16(float* c, const uint32_t* a, const uint32_t* b) {
    asm volatile(
        "mma.sync.aligned.m16n8k16.row.col.f32.bf16.bf16.f32 "
        "{%0,%1,%2,%3}, {%4,%5,%6,%7}, {%8,%9}, {%0,%1,%2,%3};"
        : "+f"(c[0]), "+f"(c[1]), "+f"(c[2]), "+f"(c[3])
        : "r"(a[0]), "r"(a[1]), "r"(a[2]), "r"(a[3]), "r"(b[0]), "r"(b[1]));
}

// ---------------- degree / norm precompute ----------------
__global__ void k_deg_init(int n) {
    int i = blockIdx.x * blockDim.x + threadIdx.x;
    if (i < n) g_deg[i] = 1.0f;
}
__global__ void k_deg_edges(const int* __restrict__ ei, const float* __restrict__ w, int E) {
    int e = blockIdx.x * blockDim.x + threadIdx.x;
    if (e < E) atomicAdd(&g_deg[ei[E + e]], w[e]);
}
__global__ void k_dinv(int n) {
    int i = blockIdx.x * blockDim.x + threadIdx.x;
    if (i < n) {
        float d = g_deg[i];
        g_dinv[i] = (d > 0.0f) ? rsqrtf(fmaxf(d, 1e-12f)) : 0.0f;
    }
}
__global__ void k_enorm(const int* __restrict__ ei, const float* __restrict__ w, int E) {
    int e = blockIdx.x * blockDim.x + threadIdx.x;
    if (e < E) g_enorm[e] = g_dinv[ei[e]] * w[e] * g_dinv[ei[E + e]];
}

// ---------------- weight transpose + bf16 split: Wt[n][k] ----------------
__global__ void k_wprep(const float* __restrict__ W, __nv_bfloat16* __restrict__ Hi,
                        __nv_bfloat16* __restrict__ Lo) {
    int i = blockIdx.x * blockDim.x + threadIdx.x;
    if (i >= 512 * 512) return;
    int k = i >> 9, n = i & 511;
    float x = W[i];
    __nv_bfloat16 h = __float2bfloat16(x);
    __nv_bfloat16 l = __float2bfloat16(x - __bfloat162float(h));
    Hi[n * 512 + k] = h;
    Lo[n * 512 + k] = l;
}

// ---------------- activation bf16 split ----------------
__global__ void k_asplit(const float4* __restrict__ X, __nv_bfloat16* __restrict__ Hi,
                         __nv_bfloat16* __restrict__ Lo, int n4) {
    int i = blockIdx.x * blockDim.x + threadIdx.x;
    if (i >= n4) return;
    float4 v = X[i];
    __nv_bfloat16 h0 = __float2bfloat16(v.x), h1 = __float2bfloat16(v.y);
    __nv_bfloat16 h2 = __float2bfloat16(v.z), h3 = __float2bfloat16(v.w);
    __nv_bfloat16 l0 = __float2bfloat16(v.x - __bfloat162float(h0));
    __nv_bfloat16 l1 = __float2bfloat16(v.y - __bfloat162float(h1));
    __nv_bfloat16 l2 = __float2bfloat16(v.z - __bfloat162float(h2));
    __nv_bfloat16 l3 = __float2bfloat16(v.w - __bfloat162float(h3));
    ((uint2*)Hi)[i] = make_uint2(pack2(h0, h1), pack2(h2, h3));
    ((uint2*)Lo)[i] = make_uint2(pack2(l0, l1), pack2(l2, l3));
}

// ---------------- mma.sync bf16-3x GEMM ----------------
// C[M,512] = A[M,512] @ W ; B operand = Wt[n][k] pre-split bf16.
// CTA tile 128x128x32, 256 thr / 8 warps (2x4), warp tile 64x32.
// 40KB stage, double buffered -> 80KB smem -> 2 CTAs/SM (16 warps).
// SMEM rows padded to 80B (conflict-free ldmatrix).
#define A_HI 0
#define A_LO 10240
#define B_HI 20480
#define B_LO 30720
#define STAGE 40960
#define GEMM_SMEM (2 * STAGE)

__global__ __launch_bounds__(256, 2) void gemm_tc(
    const __nv_bfloat16* __restrict__ Ahi, const __nv_bfloat16* __restrict__ Alo,
    const __nv_bfloat16* __restrict__ Bhi, const __nv_bfloat16* __restrict__ Blo,
    float* __restrict__ hOut, float* __restrict__ aggOut, int M) {
    extern __shared__ char smem[];
    const uint32_t sb = smem_u32(smem);
    const int tid = threadIdx.x, lane = tid & 31, wid = tid >> 5;
    const int bm = blockIdx.x * 128, bn = blockIdx.y * 128;

    // staging roles: each thread loads 1 row x 2 chunks (16B) per matrix
    const int sr = tid >> 1;              // 0..127
    const int sc = (tid & 1) * 2;         // chunk pair base (0 or 2)
    const bool av = (bm + sr) < M;
    const char* pAh = (const char*)Ahi + ((size_t)(bm + sr) * 512 + sc * 8) * 2;
    const char* pAl = (const char*)Alo + ((size_t)(bm + sr) * 512 + sc * 8) * 2;
    const char* pBh = (const char*)Bhi + ((size_t)(bn + sr) * 512 + sc * 8) * 2;
    const char* pBl = (const char*)Blo + ((size_t)(bn + sr) * 512 + sc * 8) * 2;

    auto do_stage = [&](int s, int buf) {
        const uint32_t bo = sb + buf * STAGE;
        const size_t ko = (size_t)s * 64;   // byte offset into row (32 bf16)
        const uint32_t so = (uint32_t)sr * 80 + (uint32_t)sc * 16;
        cp16(bo + A_HI + so,      pAh + ko,      av);
        cp16(bo + A_HI + so + 16, pAh + ko + 16, av);
        cp16(bo + A_LO + so,      pAl + ko,      av);
        cp16(bo + A_LO + so + 16, pAl + ko + 16, av);
        cp16(bo + B_HI + so,      pBh + ko,      true);
        cp16(bo + B_HI + so + 16, pBh + ko + 16, true);
        cp16(bo + B_LO + so,      pBl + ko,      true);
        cp16(bo + B_LO + so + 16, pBl + ko + 16, true);
        CP_COMMIT();
    };

    const int wm = (wid >> 2) * 64;   // 0 / 64
    const int wn = (wid & 3) * 32;    // 0..96

    float acc[4][4][4];
#pragma unroll
    for (int i = 0; i < 4; i++)
#pragma unroll
        for (int j = 0; j < 4; j++)
#pragma unroll
            for (int k = 0; k < 4; k++) acc[i][j][k] = 0.0f;

    do_stage(0, 0);

    for (int s = 0; s < 16; ++s) {
        if (s + 1 < 16) do_stage(s + 1, (s + 1) & 1);
        if (s + 1 < 16) CP_WAIT1(); else CP_WAIT0();
        __syncthreads();

        const uint32_t bufb = sb + (s & 1) * STAGE;
#pragma unroll
        for (int kk = 0; kk < 2; ++kk) {
            const int k16 = kk * 16;
            uint32_t ah[4][4], al[4][4];
#pragma unroll
            for (int ma = 0; ma < 4; ++ma) {
                uint32_t aaddr = bufb + A_HI +
                    (uint32_t)(wm + ma * 16 + (lane & 15)) * 80 +
                    (uint32_t)(k16 + ((lane >> 4) << 3)) * 2;
                LDSM_X4(ah[ma], aaddr);
                LDSM_X4(al[ma], aaddr + (A_LO - A_HI));
            }
#pragma unroll
            for (int na = 0; na < 4; ++na) {
                uint32_t baddr = bufb + B_HI +
                    (uint32_t)(wn + na * 8 + (lane & 7)) * 80 +
                    (uint32_t)(k16 + (((lane >> 3) & 1) << 3)) * 2;
                uint32_t bh[2], bl[2];
                LDSM_X2(bh, baddr);
                LDSM_X2(bl, baddr + (B_LO - B_HI));
#pragma unroll
                for (int ma = 0; ma < 4; ++ma) {
                    mma_bf16(acc[ma][na], ah[ma], bh);
                    mma_bf16(acc[ma][na], al[ma], bh);
                    mma_bf16(acc[ma][na], ah[ma], bl);
                }
            }
        }
        __syncthreads();
    }

    // epilogue: write h and agg = dinv^2 * h
#pragma unroll
    for (int ma = 0; ma < 4; ++ma) {
        int r0 = bm + wm + ma * 16 + (lane >> 2);
        int r1 = r0 + 8;
        float d0 = 0.f, d1 = 0.f;
        if (r0 < M) { float t = g_dinv[r0]; d0 = t * t; }
        if (r1 < M) { float t = g_dinv[r1]; d1 = t * t; }
#pragma unroll
        for (int na = 0; na < 4; ++na) {
            int col = bn + wn + na * 8 + 2 * (lane & 3);
            float* c = acc[ma][na];
            if (r0 < M) {
                size_t o = (size_t)r0 * 512 + col;
                *(float2*)&hOut[o]   = make_float2(c[0], c[1]);
                *(float2*)&aggOut[o] = make_float2(c[0] * d0, c[1] * d0);
            }
            if (r1 < M) {
                size_t o = (size_t)r1 * 512 + col;
                *(float2*)&hOut[o]   = make_float2(c[2], c[3]);
                *(float2*)&aggOut[o] = make_float2(c[2] * d1, c[3] * d1);
            }
        }
    }
}

// ---------------- edge scatter: agg[col] += enorm * h[row] ----------------
__global__ void k_scatter(const float* __restrict__ h, float* __restrict__ agg,
                          const int* __restrict__ ei, int E) {
    int e = blockIdx.x * (blockDim.x >> 5) + (threadIdx.x >> 5);
    if (e >= E) return;
    int lane = threadIdx.x & 31;
    int r = ei[e], c = ei[E + e];
    float nm = g_enorm[e];
    const float* hr = h + (size_t)r * 512;
    float* ac = agg + (size_t)c * 512;
#pragma unroll
    for (int j = 0; j < 16; j++)
        atomicAdd(ac + lane + j * 32, nm * hr[lane + j * 32]);
}

// ---------------- epilogue: relu -> L2 norm -> residual avg (+ opt bf16 split)
__global__ __launch_bounds__(128) void k_epilogue(const float* __restrict__ agg,
                                                  const float* __restrict__ bias,
                                                  const float* __restrict__ resid,
                                                  float* __restrict__ out,
                                                  __nv_bfloat16* __restrict__ hi,
                                                  __nv_bfloat16* __restrict__ lo,
                                                  int n) {
    int node = blockIdx.x;
    if (node >= n) return;
    int tid = threadIdx.x;
    const float4* ag = (const float4*)(agg + (size_t)node * 512);
    const float4* rs = (const float4*)(resid + (size_t)node * 512);
    const float4* bi = (const float4*)bias;
    float4* ot = (float4*)(out + (size_t)node * 512);

    float4 v = ag[tid];
    float4 b = bi[tid];
    v.x = fmaxf(v.x + b.x, 0.0f);
    v.y = fmaxf(v.y + b.y, 0.0f);
    v.z = fmaxf(v.z + b.z, 0.0f);
    v.w = fmaxf(v.w + b.w, 0.0f);

    float s = v.x * v.x + v.y * v.y + v.z * v.z + v.w * v.w;
#pragma unroll
    for (int off = 16; off > 0; off >>= 1)
        s += __shfl_down_sync(0xFFFFFFFFu, s, off);

    __shared__ float warp_s[4];
    __shared__ float s_total;
    if ((tid & 31) == 0) warp_s[tid >> 5] = s;
    __syncthreads();
    if (tid == 0) s_total = warp_s[0] + warp_s[1] + warp_s[2] + warp_s[3];
    __syncthreads();

    float inv = 0.5f / fmaxf(sqrtf(s_total), 1e-12f);
    float4 r = rs[tid];
    float4 o = make_float4(v.x * inv + r.x * 0.5f, v.y * inv + r.y * 0.5f,
                           v.z * inv + r.z * 0.5f, v.w * inv + r.w * 0.5f);
    ot[tid] = o;
    if (hi) {
        __nv_bfloat16 h0 = __float2bfloat16(o.x), h1 = __float2bfloat16(o.y);
        __nv_bfloat16 h2 = __float2bfloat16(o.z), h3 = __float2bfloat16(o.w);
        __nv_bfloat16 l0 = __float2bfloat16(o.x - __bfloat162float(h0));
        __nv_bfloat16 l1 = __float2bfloat16(o.y - __bfloat162float(h1));
        __nv_bfloat16 l2 = __float2bfloat16(o.z - __bfloat162float(h2));
        __nv_bfloat16 l3 = __float2bfloat16(o.w - __bfloat162float(h3));
        size_t idx = (size_t)node * 128 + tid;   // uint2 units (4 bf16)
        ((uint2*)hi)[idx] = make_uint2(pack2(h0, h1), pack2(h2, h3));
        ((uint2*)lo)[idx] = make_uint2(pack2(l0, l1), pack2(l2, l3));
    }
}

// ---------------- final projection: p[i,0:2] = h[i,:] @ Wf ----------------
__global__ __launch_bounds__(256) void k_pdot(const float* __restrict__ h,
                                              const float* __restrict__ Wf, int n) {
    __shared__ float sWf[1024];
    int tid = threadIdx.x;
#pragma unroll
    for (int i = tid; i < 1024; i += 256) sWf[i] = Wf[i];
    __syncthreads();

    int node = blockIdx.x * 8 + (tid >> 5);
    if (node >= n) return;
    int lane = tid & 31;
    const float* hr = h + (size_t)node * 512;
    float s0 = 0.f, s1 = 0.f;
#pragma unroll
    for (int j = 0; j < 16; j++) {
        int k = lane + j * 32;
        float hv = hr[k];
        s0 += hv * sWf[k * 2];
        s1 += hv * sWf[k * 2 + 1];
    }
#pragma unroll
    for (int off = 16; off > 0; off >>= 1) {
        s0 += __shfl_down_sync(0xFFFFFFFFu, s0, off);
        s1 += __shfl_down_sync(0xFFFFFFFFu, s1, off);
    }
    if (lane == 0) {
        g_p[node * 2]     = s0;
        g_p[node * 2 + 1] = s1;
    }
}

__global__ void k_pagg_init(int n) {
    int i = blockIdx.x * blockDim.x + threadIdx.x;
    if (i >= n) return;
    float s = g_dinv[i]; s = s * s;
    g_pagg[i * 2]     = s * g_p[i * 2];
    g_pagg[i * 2 + 1] = s * g_p[i * 2 + 1];
}

__global__ void k_pscatter(const int* __restrict__ ei, int E) {
    int e = blockIdx.x * blockDim.x + threadIdx.x;
    if (e >= E) return;
    int r = ei[e], c = ei[E + e];
    float nm = g_enorm[e];
    atomicAdd(&g_pagg[c * 2],     nm * g_p[r * 2]);
    atomicAdd(&g_pagg[c * 2 + 1], nm * g_p[r * 2 + 1]);
}

__global__ void k_lsm(const float* __restrict__ bf, int n) {
    int i = blockIdx.x * blockDim.x + threadIdx.x;
    if (i >= n) return;
    float z0 = g_pagg[i * 2] + bf[0];
    float z1 = g_pagg[i * 2 + 1] + bf[1];
    float m = fmaxf(z0, z1);
    float lse = m + logf(expf(z0 - m) + expf(z1 - m));
    g_ls[i * 2]     = z0 - lse;
    g_ls[i * 2 + 1] = z1 - lse;
}

__global__ void k_pred(const int* __restrict__ pe, float* __restrict__ out, int NP) {
    int p = blockIdx.x * blockDim.x + threadIdx.x;
    if (p >= NP) return;
    int u = pe[p], v = pe[NP + p];
    out[p * 2]     = -(g_ls[u * 2]     * g_ls[v * 2]);
    out[p * 2 + 1] = -(g_ls[u * 2 + 1] * g_ls[v * 2 + 1]);
}

// ---------------- launch ----------------
extern "C" void kernel_launch(void* const* d_in, const int* in_sizes, int n_in,
                              void* d_out, int out_size) {
    const float* x   = (const float*)d_in[0];
    const int*   ei  = (const int*)d_in[1];
    const float* w   = (const float*)d_in[2];
    const int*   pe  = (const int*)d_in[3];
    const float* W1  = (const float*)d_in[4];
    const float* b1  = (const float*)d_in[5];
    const float* W2  = (const float*)d_in[6];
    const float* b2  = (const float*)d_in[7];
    const float* Wf  = (const float*)d_in[8];
    const float* bf  = (const float*)d_in[9];
    float* out = (float*)d_out;

    const int N  = in_sizes[0] / DDIM;
    const int E  = in_sizes[2];
    const int NP = in_sizes[3] / 2;

    float *hbuf, *aggbuf, *x1buf;
    __nv_bfloat16 *ahi, *alo, *w1h, *w1l, *w2h, *w2l;
    cudaGetSymbolAddress((void**)&hbuf,   g_h);
    cudaGetSymbolAddress((void**)&aggbuf, g_agg);
    cudaGetSymbolAddress((void**)&x1buf,  g_x1);
    cudaGetSymbolAddress((void**)&ahi, g_Ahi);
    cudaGetSymbolAddress((void**)&alo, g_Alo);
    cudaGetSymbolAddress((void**)&w1h, g_W1h);
    cudaGetSymbolAddress((void**)&w1l, g_W1l);
    cudaGetSymbolAddress((void**)&w2h, g_W2h);
    cudaGetSymbolAddress((void**)&w2l, g_W2l);

    cudaFuncSetAttribute(gemm_tc, cudaFuncAttributeMaxDynamicSharedMemorySize,
                         GEMM_SMEM);

    dim3 ggrid((N + 127) / 128, 4);
    const int n4 = N * (DDIM / 4);

    // precompute
    k_deg_init <<<(N + 255) / 256, 256>>>(N);
    k_deg_edges<<<(E + 255) / 256, 256>>>(ei, w, E);
    k_dinv     <<<(N + 255) / 256, 256>>>(N);
    k_enorm    <<<(E + 255) / 256, 256>>>(ei, w, E);
    k_wprep    <<<(512 * 512 + 255) / 256, 256>>>(W1, w1h, w1l);
    k_wprep    <<<(512 * 512 + 255) / 256, 256>>>(W2, w2h, w2l);
    k_asplit   <<<(n4 + 255) / 256, 256>>>((const float4*)x, ahi, alo, n4);

    // ---- layer 1 ----
    gemm_tc   <<<ggrid, 256, GEMM_SMEM>>>(ahi, alo, w1h, w1l, hbuf, aggbuf, N);
    k_scatter <<<(E + 7) / 8, 256>>>(hbuf, aggbuf, ei, E);
    k_epilogue<<<N, 128>>>(aggbuf, b1, x, x1buf, ahi, alo, N);   // fused split for L2

    // ---- layer 2 ----
    gemm_tc   <<<ggrid, 256, GEMM_SMEM>>>(ahi, alo, w2h, w2l, hbuf, aggbuf, N);
    k_scatter <<<(E + 7) / 8, 256>>>(hbuf, aggbuf, ei, E);
    k_epilogue<<<N, 128>>>(aggbuf, b2, x1buf, hbuf,
                           (__nv_bfloat16*)0, (__nv_bfloat16*)0, N);

    // ---- final conv (512 -> 2) + log_softmax ----
    k_pdot     <<<(N + 7) / 8, 256>>>(hbuf, Wf, N);
    k_pagg_init<<<(N + 255) / 256, 256>>>(N);
    k_pscatter <<<(E + 255) / 256, 256>>>(ei, E);
    k_lsm      <<<(N + 255) / 256, 256>>>(bf, N);

    // ---- predictor edges ----
    k_pred<<<(NP + 255) / 256, 256>>>(pe, out, NP);
}

// round 7
// speedup vs baseline: 1.8612x; 1.4340x over previous
#include <cuda_runtime.h>
#include <cuda_bf16.h>
#include <math.h>
#include <stdint.h>

#define NNODES 100000
#define NEDGES 150000
#define NPRED  200000
#define DDIM   512

// ---------------- scratch (no allocs allowed) ----------------
__device__ float g_h  [(size_t)NNODES * DDIM];
__device__ float g_agg[(size_t)NNODES * DDIM];
__device__ float g_x1 [(size_t)NNODES * DDIM];
__device__ __nv_bfloat16 g_Ahi[(size_t)NNODES * DDIM];
__device__ __nv_bfloat16 g_Alo[(size_t)NNODES * DDIM];
__device__ __nv_bfloat16 g_W1h[512 * 512];
__device__ __nv_bfloat16 g_W1l[512 * 512];
__device__ __nv_bfloat16 g_W2h[512 * 512];
__device__ __nv_bfloat16 g_W2l[512 * 512];
__device__ float g_deg [NNODES];
__device__ float g_dinv[NNODES];
__device__ float g_enorm[NEDGES];
__device__ float g_p   [NNODES * 2];
__device__ float g_pagg[NNODES * 2];
__device__ float g_ls  [NNODES * 2];

// ---------------- helpers ----------------
__device__ __forceinline__ uint32_t smem_u32(const void* p) {
    uint32_t a;
    asm("{ .reg .u64 t; cvta.to.shared.u64 t, %1; cvt.u32.u64 %0, t; }" : "=r"(a) : "l"(p));
    return a;
}
__device__ __forceinline__ uint32_t pack2(__nv_bfloat16 a, __nv_bfloat16 b) {
    return (uint32_t)__bfloat16_as_ushort(a) | ((uint32_t)__bfloat16_as_ushort(b) << 16);
}
__device__ __forceinline__ void cp16(uint32_t dst, const void* src, bool p) {
    asm volatile("cp.async.cg.shared.global [%0], [%1], 16, %2;"
                 :: "r"(dst), "l"(src), "r"(p ? 16 : 0) : "memory");
}
#define CP_COMMIT() asm volatile("cp.async.commit_group;" ::: "memory")
#define CP_WAIT2()  asm volatile("cp.async.wait_group 2;" ::: "memory")
#define CP_WAIT1()  asm volatile("cp.async.wait_group 1;" ::: "memory")
#define CP_WAIT0()  asm volatile("cp.async.wait_group 0;" ::: "memory")
#define LDSM_X4(r, a) asm volatile( \
    "ldmatrix.sync.aligned.m8n8.x4.shared.b16 {%0,%1,%2,%3}, [%4];" \
    : "=r"((r)[0]), "=r"((r)[1]), "=r"((r)[2]), "=r"((r)[3]) : "r"(a))
#define LDSM_X2(r, a) asm volatile( \
    "ldmatrix.sync.aligned.m8n8.x2.shared.b16 {%0,%1}, [%2];" \
    : "=r"((r)[0]), "=r"((r)[1]) : "r"(a))

__device__ __forceinline__ void mma_bf16(float* c, const uint32_t* a, const uint32_t* b) {
    asm volatile(
        "mma.sync.aligned.m16n8k16.row.col.f32.bf16.bf16.f32 "
        "{%0,%1,%2,%3}, {%4,%5,%6,%7}, {%8,%9}, {%0,%1,%2,%3};"
        : "+f"(c[0]), "+f"(c[1]), "+f"(c[2]), "+f"(c[3])
        : "r"(a[0]), "r"(a[1]), "r"(a[2]), "r"(a[3]), "r"(b[0]), "r"(b[1]));
}

// ---------------- degree / norm precompute ----------------
__global__ void k_deg_init(int n) {
    int i = blockIdx.x * blockDim.x + threadIdx.x;
    if (i < n) g_deg[i] = 1.0f;
}
__global__ void k_deg_edges(const int* __restrict__ ei, const float* __restrict__ w, int E) {
    int e = blockIdx.x * blockDim.x + threadIdx.x;
    if (e < E) atomicAdd(&g_deg[ei[E + e]], w[e]);
}
__global__ void k_dinv(int n) {
    int i = blockIdx.x * blockDim.x + threadIdx.x;
    if (i < n) {
        float d = g_deg[i];
        g_dinv[i] = (d > 0.0f) ? rsqrtf(fmaxf(d, 1e-12f)) : 0.0f;
    }
}
__global__ void k_enorm(const int* __restrict__ ei, const float* __restrict__ w, int E) {
    int e = blockIdx.x * blockDim.x + threadIdx.x;
    if (e < E) g_enorm[e] = g_dinv[ei[e]] * w[e] * g_dinv[ei[E + e]];
}

// ---------------- weight transpose + bf16 split: Wt[n][k] ----------------
__global__ void k_wprep(const float* __restrict__ W, __nv_bfloat16* __restrict__ Hi,
                        __nv_bfloat16* __restrict__ Lo) {
    int i = blockIdx.x * blockDim.x + threadIdx.x;
    if (i >= 512 * 512) return;
    int k = i >> 9, n = i & 511;
    float x = W[i];
    __nv_bfloat16 h = __float2bfloat16(x);
    __nv_bfloat16 l = __float2bfloat16(x - __bfloat162float(h));
    Hi[n * 512 + k] = h;
    Lo[n * 512 + k] = l;
}

// ---------------- activation bf16 split ----------------
__global__ void k_asplit(const float4* __restrict__ X, __nv_bfloat16* __restrict__ Hi,
                         __nv_bfloat16* __restrict__ Lo, int n4) {
    int i = blockIdx.x * blockDim.x + threadIdx.x;
    if (i >= n4) return;
    float4 v = X[i];
    __nv_bfloat16 h0 = __float2bfloat16(v.x), h1 = __float2bfloat16(v.y);
    __nv_bfloat16 h2 = __float2bfloat16(v.z), h3 = __float2bfloat16(v.w);
    __nv_bfloat16 l0 = __float2bfloat16(v.x - __bfloat162float(h0));
    __nv_bfloat16 l1 = __float2bfloat16(v.y - __bfloat162float(h1));
    __nv_bfloat16 l2 = __float2bfloat16(v.z - __bfloat162float(h2));
    __nv_bfloat16 l3 = __float2bfloat16(v.w - __bfloat162float(h3));
    ((uint2*)Hi)[i] = make_uint2(pack2(h0, h1), pack2(h2, h3));
    ((uint2*)Lo)[i] = make_uint2(pack2(l0, l1), pack2(l2, l3));
}

// ---------------- mma.sync bf16-3x GEMM, 4-stage pipeline ----------------
// C[M,512] = A[M,512] @ W ; B operand = Wt[n][k] pre-split bf16.
// CTA tile 128x128, K step 16, 4-stage cp.async ring (one barrier per step).
// Stage = 4 matrices x 128 rows x 48B pitch (32B data) = 24KB; 4 stages = 96KB.
// 2 CTAs/SM. 48B pitch -> conflict-free ldmatrix phases.
#define PITCH   48
#define MAT_SZ  (128 * PITCH)      // 6144
#define A_HI 0
#define A_LO (1 * MAT_SZ)
#define B_HI (2 * MAT_SZ)
#define B_LO (3 * MAT_SZ)
#define STAGE (4 * MAT_SZ)         // 24576
#define NSTG 4
#define GEMM_SMEM (NSTG * STAGE)   // 98304

__global__ __launch_bounds__(256, 2) void gemm_tc(
    const __nv_bfloat16* __restrict__ Ahi, const __nv_bfloat16* __restrict__ Alo,
    const __nv_bfloat16* __restrict__ Bhi, const __nv_bfloat16* __restrict__ Blo,
    float* __restrict__ hOut, float* __restrict__ aggOut, int M) {
    extern __shared__ char smem[];
    const uint32_t sb = smem_u32(smem);
    const int tid = threadIdx.x, lane = tid & 31, wid = tid >> 5;
    const int bm = blockIdx.x * 128, bn = blockIdx.y * 128;

    // staging: each thread loads 16B (half a 32B row) per matrix per stage
    const int sr = tid >> 1;                  // row 0..127
    const uint32_t sc = (uint32_t)(tid & 1) * 16;
    const bool av = (bm + sr) < M;
    const char* pAh = (const char*)Ahi + ((size_t)(bm + sr) * 512) * 2 + (tid & 1) * 16;
    const char* pAl = (const char*)Alo + ((size_t)(bm + sr) * 512) * 2 + (tid & 1) * 16;
    const char* pBh = (const char*)Bhi + ((size_t)(bn + sr) * 512) * 2 + (tid & 1) * 16;
    const char* pBl = (const char*)Blo + ((size_t)(bn + sr) * 512) * 2 + (tid & 1) * 16;
    const uint32_t so = (uint32_t)sr * PITCH + sc;

    auto do_stage = [&](int s) {
        const uint32_t bo = sb + (uint32_t)(s & 3) * STAGE;
        const size_t ko = (size_t)s * 32;     // 16 bf16 = 32B per row per stage
        cp16(bo + A_HI + so, pAh + ko, av);
        cp16(bo + A_LO + so, pAl + ko, av);
        cp16(bo + B_HI + so, pBh + ko, true);
        cp16(bo + B_LO + so, pBl + ko, true);
        CP_COMMIT();
    };

    const int wm = (wid >> 2) * 64;   // 0 / 64
    const int wn = (wid & 3) * 32;    // 0..96

    float acc[4][4][4];
#pragma unroll
    for (int i = 0; i < 4; i++)
#pragma unroll
        for (int j = 0; j < 4; j++)
#pragma unroll
            for (int k = 0; k < 4; k++) acc[i][j][k] = 0.0f;

    do_stage(0); do_stage(1); do_stage(2);

#pragma unroll 1
    for (int s = 0; s < 32; ++s) {
        // stage s must have landed; keep 2 newer stages in flight
        if (s <= 29) CP_WAIT2();
        else if (s == 30) CP_WAIT1();
        else CP_WAIT0();
        __syncthreads();
        if (s + 3 < 32) do_stage(s + 3);   // overwrites buffer (s-1)&3: safe after sync

        const uint32_t bufb = sb + (uint32_t)(s & 3) * STAGE;
        uint32_t ah[4][4], al[4][4];
#pragma unroll
        for (int ma = 0; ma < 4; ++ma) {
            uint32_t aaddr = bufb + A_HI +
                (uint32_t)(wm + ma * 16 + (lane & 15)) * PITCH + ((lane >> 4) << 4);
            LDSM_X4(ah[ma], aaddr);
            LDSM_X4(al[ma], aaddr + (A_LO - A_HI));
        }
#pragma unroll
        for (int na = 0; na < 4; ++na) {
            uint32_t baddr = bufb + B_HI +
                (uint32_t)(wn + na * 8 + (lane & 7)) * PITCH + (((lane >> 3) & 1) << 4);
            uint32_t bh[2], bl[2];
            LDSM_X2(bh, baddr);
            LDSM_X2(bl, baddr + (B_LO - B_HI));
#pragma unroll
            for (int ma = 0; ma < 4; ++ma) {
                mma_bf16(acc[ma][na], ah[ma], bh);
                mma_bf16(acc[ma][na], al[ma], bh);
                mma_bf16(acc[ma][na], ah[ma], bl);
            }
        }
    }

    // epilogue: write h and agg = dinv^2 * h
#pragma unroll
    for (int ma = 0; ma < 4; ++ma) {
        int r0 = bm + wm + ma * 16 + (lane >> 2);
        int r1 = r0 + 8;
        float d0 = 0.f, d1 = 0.f;
        if (r0 < M) { float t = g_dinv[r0]; d0 = t * t; }
        if (r1 < M) { float t = g_dinv[r1]; d1 = t * t; }
#pragma unroll
        for (int na = 0; na < 4; ++na) {
            int col = bn + wn + na * 8 + 2 * (lane & 3);
            float* c = acc[ma][na];
            if (r0 < M) {
                size_t o = (size_t)r0 * 512 + col;
                *(float2*)&hOut[o]   = make_float2(c[0], c[1]);
                *(float2*)&aggOut[o] = make_float2(c[0] * d0, c[1] * d0);
            }
            if (r1 < M) {
                size_t o = (size_t)r1 * 512 + col;
                *(float2*)&hOut[o]   = make_float2(c[2], c[3]);
                *(float2*)&aggOut[o] = make_float2(c[2] * d1, c[3] * d1);
            }
        }
    }
}

// ---------------- edge scatter: agg[col] += enorm * h[row] ----------------
__global__ void k_scatter(const float* __restrict__ h, float* __restrict__ agg,
                          const int* __restrict__ ei, int E) {
    int e = blockIdx.x * (blockDim.x >> 5) + (threadIdx.x >> 5);
    if (e >= E) return;
    int lane = threadIdx.x & 31;
    int r = ei[e], c = ei[E + e];
    float nm = g_enorm[e];
    const float* hr = h + (size_t)r * 512;
    float* ac = agg + (size_t)c * 512;
#pragma unroll
    for (int j = 0; j < 16; j++)
        atomicAdd(ac + lane + j * 32, nm * hr[lane + j * 32]);
}

// ---------------- epilogue: relu -> L2 norm -> residual avg (+ opt bf16 split)
__global__ __launch_bounds__(128) void k_epilogue(const float* __restrict__ agg,
                                                  const float* __restrict__ bias,
                                                  const float* __restrict__ resid,
                                                  float* __restrict__ out,
                                                  __nv_bfloat16* __restrict__ hi,
                                                  __nv_bfloat16* __restrict__ lo,
                                                  int n) {
    int node = blockIdx.x;
    if (node >= n) return;
    int tid = threadIdx.x;
    const float4* ag = (const float4*)(agg + (size_t)node * 512);
    const float4* rs = (const float4*)(resid + (size_t)node * 512);
    const float4* bi = (const float4*)bias;
    float4* ot = (float4*)(out + (size_t)node * 512);

    float4 v = ag[tid];
    float4 b = bi[tid];
    v.x = fmaxf(v.x + b.x, 0.0f);
    v.y = fmaxf(v.y + b.y, 0.0f);
    v.z = fmaxf(v.z + b.z, 0.0f);
    v.w = fmaxf(v.w + b.w, 0.0f);

    float s = v.x * v.x + v.y * v.y + v.z * v.z + v.w * v.w;
#pragma unroll
    for (int off = 16; off > 0; off >>= 1)
        s += __shfl_down_sync(0xFFFFFFFFu, s, off);

    __shared__ float warp_s[4];
    __shared__ float s_total;
    if ((tid & 31) == 0) warp_s[tid >> 5] = s;
    __syncthreads();
    if (tid == 0) s_total = warp_s[0] + warp_s[1] + warp_s[2] + warp_s[3];
    __syncthreads();

    float inv = 0.5f / fmaxf(sqrtf(s_total), 1e-12f);
    float4 r = rs[tid];
    float4 o = make_float4(v.x * inv + r.x * 0.5f, v.y * inv + r.y * 0.5f,
                           v.z * inv + r.z * 0.5f, v.w * inv + r.w * 0.5f);
    ot[tid] = o;
    if (hi) {
        __nv_bfloat16 h0 = __float2bfloat16(o.x), h1 = __float2bfloat16(o.y);
        __nv_bfloat16 h2 = __float2bfloat16(o.z), h3 = __float2bfloat16(o.w);
        __nv_bfloat16 l0 = __float2bfloat16(o.x - __bfloat162float(h0));
        __nv_bfloat16 l1 = __float2bfloat16(o.y - __bfloat162float(h1));
        __nv_bfloat16 l2 = __float2bfloat16(o.z - __bfloat162float(h2));
        __nv_bfloat16 l3 = __float2bfloat16(o.w - __bfloat162float(h3));
        size_t idx = (size_t)node * 128 + tid;   // uint2 units (4 bf16)
        ((uint2*)hi)[idx] = make_uint2(pack2(h0, h1), pack2(h2, h3));
        ((uint2*)lo)[idx] = make_uint2(pack2(l0, l1), pack2(l2, l3));
    }
}

// ---------------- final projection: p[i,0:2] = h[i,:] @ Wf ----------------
__global__ __launch_bounds__(256) void k_pdot(const float* __restrict__ h,
                                              const float* __restrict__ Wf, int n) {
    __shared__ float sWf[1024];
    int tid = threadIdx.x;
#pragma unroll
    for (int i = tid; i < 1024; i += 256) sWf[i] = Wf[i];
    __syncthreads();

    int node = blockIdx.x * 8 + (tid >> 5);
    if (node >= n) return;
    int lane = tid & 31;
    const float* hr = h + (size_t)node * 512;
    float s0 = 0.f, s1 = 0.f;
#pragma unroll
    for (int j = 0; j < 16; j++) {
        int k = lane + j * 32;
        float hv = hr[k];
        s0 += hv * sWf[k * 2];
        s1 += hv * sWf[k * 2 + 1];
    }
#pragma unroll
    for (int off = 16; off > 0; off >>= 1) {
        s0 += __shfl_down_sync(0xFFFFFFFFu, s0, off);
        s1 += __shfl_down_sync(0xFFFFFFFFu, s1, off);
    }
    if (lane == 0) {
        float t = g_dinv[node], s = t * t;
        g_p[node * 2]        = s0;
        g_p[node * 2 + 1]    = s1;
        g_pagg[node * 2]     = s * s0;   // fused self-loop init
        g_pagg[node * 2 + 1] = s * s1;
    }
}

__global__ void k_pscatter(const int* __restrict__ ei, int E) {
    int e = blockIdx.x * blockDim.x + threadIdx.x;
    if (e >= E) return;
    int r = ei[e], c = ei[E + e];
    float nm = g_enorm[e];
    atomicAdd(&g_pagg[c * 2],     nm * g_p[r * 2]);
    atomicAdd(&g_pagg[c * 2 + 1], nm * g_p[r * 2 + 1]);
}

__global__ void k_lsm(const float* __restrict__ bf, int n) {
    int i = blockIdx.x * blockDim.x + threadIdx.x;
    if (i >= n) return;
    float z0 = g_pagg[i * 2] + bf[0];
    float z1 = g_pagg[i * 2 + 1] + bf[1];
    float m = fmaxf(z0, z1);
    float lse = m + logf(expf(z0 - m) + expf(z1 - m));
    g_ls[i * 2]     = z0 - lse;
    g_ls[i * 2 + 1] = z1 - lse;
}

__global__ void k_pred(const int* __restrict__ pe, float* __restrict__ out, int NP) {
    int p = blockIdx.x * blockDim.x + threadIdx.x;
    if (p >= NP) return;
    int u = pe[p], v = pe[NP + p];
    out[p * 2]     = -(g_ls[u * 2]     * g_ls[v * 2]);
    out[p * 2 + 1] = -(g_ls[u * 2 + 1] * g_ls[v * 2 + 1]);
}

// ---------------- launch ----------------
extern "C" void kernel_launch(void* const* d_in, const int* in_sizes, int n_in,
                              void* d_out, int out_size) {
    const float* x   = (const float*)d_in[0];
    const int*   ei  = (const int*)d_in[1];
    const float* w   = (const float*)d_in[2];
    const int*   pe  = (const int*)d_in[3];
    const float* W1  = (const float*)d_in[4];
    const float* b1  = (const float*)d_in[5];
    const float* W2  = (const float*)d_in[6];
    const float* b2  = (const float*)d_in[7];
    const float* Wf  = (const float*)d_in[8];
    const float* bf  = (const float*)d_in[9];
    float* out = (float*)d_out;

    const int N  = in_sizes[0] / DDIM;
    const int E  = in_sizes[2];
    const int NP = in_sizes[3] / 2;

    float *hbuf, *aggbuf, *x1buf;
    __nv_bfloat16 *ahi, *alo, *w1h, *w1l, *w2h, *w2l;
    cudaGetSymbolAddress((void**)&hbuf,   g_h);
    cudaGetSymbolAddress((void**)&aggbuf, g_agg);
    cudaGetSymbolAddress((void**)&x1buf,  g_x1);
    cudaGetSymbolAddress((void**)&ahi, g_Ahi);
    cudaGetSymbolAddress((void**)&alo, g_Alo);
    cudaGetSymbolAddress((void**)&w1h, g_W1h);
    cudaGetSymbolAddress((void**)&w1l, g_W1l);
    cudaGetSymbolAddress((void**)&w2h, g_W2h);
    cudaGetSymbolAddress((void**)&w2l, g_W2l);

    cudaFuncSetAttribute(gemm_tc, cudaFuncAttributeMaxDynamicSharedMemorySize,
                         GEMM_SMEM);

    dim3 ggrid((N + 127) / 128, 4);
    const int n4 = N * (DDIM / 4);

    // precompute
    k_deg_init <<<(N + 255) / 256, 256>>>(N);
    k_deg_edges<<<(E + 255) / 256, 256>>>(ei, w, E);
    k_dinv     <<<(N + 255) / 256, 256>>>(N);
    k_enorm    <<<(E + 255) / 256, 256>>>(ei, w, E);
    k_wprep    <<<(512 * 512 + 255) / 256, 256>>>(W1, w1h, w1l);
    k_wprep    <<<(512 * 512 + 255) / 256, 256>>>(W2, w2h, w2l);
    k_asplit   <<<(n4 + 255) / 256, 256>>>((const float4*)x, ahi, alo, n4);

    // ---- layer 1 ----
    gemm_tc   <<<ggrid, 256, GEMM_SMEM>>>(ahi, alo, w1h, w1l, hbuf, aggbuf, N);
    k_scatter <<<(E + 7) / 8, 256>>>(hbuf, aggbuf, ei, E);
    k_epilogue<<<N, 128>>>(aggbuf, b1, x, x1buf, ahi, alo, N);   // fused split for L2

    // ---- layer 2 ----
    gemm_tc   <<<ggrid, 256, GEMM_SMEM>>>(ahi, alo, w2h, w2l, hbuf, aggbuf, N);
    k_scatter <<<(E + 7) / 8, 256>>>(hbuf, aggbuf, ei, E);
    k_epilogue<<<N, 128>>>(aggbuf, b2, x1buf, hbuf,
                           (__nv_bfloat16*)0, (__nv_bfloat16*)0, N);

    // ---- final conv (512 -> 2) + log_softmax ----
    k_pdot    <<<(N + 7) / 8, 256>>>(hbuf, Wf, N);
    k_pscatter<<<(E + 255) / 256, 256>>>(ei, E);
    k_lsm     <<<(N + 255) / 256, 256>>>(bf, N);

    // ---- predictor edges ----
    k_pred<<<(NP + 255) / 256, 256>>>(pe, out, NP);
}

// round 11
// speedup vs baseline: 2.0717x; 1.1131x over previous
#include <cuda_runtime.h>
#include <cuda_bf16.h>
#include <math.h>
#include <stdint.h>

#define NNODES 100000
#define NEDGES 150000
#define NPRED  200000
#define DDIM   512

// ---------------- scratch (no allocs allowed) ----------------
__device__ float g_h  [(size_t)NNODES * DDIM];
__device__ float g_x1 [(size_t)NNODES * DDIM];
__device__ __nv_bfloat16 g_Ahi[(size_t)NNODES * DDIM];
__device__ __nv_bfloat16 g_Alo[(size_t)NNODES * DDIM];
__device__ __nv_bfloat16 g_W1h[512 * 512];
__device__ __nv_bfloat16 g_W1l[512 * 512];
__device__ __nv_bfloat16 g_W2h[512 * 512];
__device__ __nv_bfloat16 g_W2l[512 * 512];
__device__ float g_deg [NNODES];
__device__ float g_dinv[NNODES];
__device__ float g_enorm[NEDGES];
__device__ float g_p   [NNODES * 2];
__device__ float g_ls  [NNODES * 2];
// CSR (edges grouped by destination col)
__device__ int g_cnt   [NNODES];
__device__ int g_rstart[NNODES + 1];
__device__ int g_cursor[NNODES];
__device__ int g_csre  [NEDGES];
__device__ int g_bsum  [512];

// ---------------- helpers ----------------
__device__ __forceinline__ uint32_t smem_u32(const void* p) {
    uint32_t a;
    asm("{ .reg .u64 t; cvta.to.shared.u64 t, %1; cvt.u32.u64 %0, t; }" : "=r"(a) : "l"(p));
    return a;
}
__device__ __forceinline__ uint32_t pack2(__nv_bfloat16 a, __nv_bfloat16 b) {
    return (uint32_t)__bfloat16_as_ushort(a) | ((uint32_t)__bfloat16_as_ushort(b) << 16);
}
__device__ __forceinline__ void cp16(uint32_t dst, const void* src, bool p) {
    asm volatile("cp.async.cg.shared.global [%0], [%1], 16, %2;"
                 :: "r"(dst), "l"(src), "r"(p ? 16 : 0) : "memory");
}
#define CP_COMMIT() asm volatile("cp.async.commit_group;" ::: "memory")
#define CP_WAIT2()  asm volatile("cp.async.wait_group 2;" ::: "memory")
#define CP_WAIT1()  asm volatile("cp.async.wait_group 1;" ::: "memory")
#define CP_WAIT0()  asm volatile("cp.async.wait_group 0;" ::: "memory")
#define LDSM_X4(r, a) asm volatile( \
    "ldmatrix.sync.aligned.m8n8.x4.shared.b16 {%0,%1,%2,%3}, [%4];" \
    : "=r"((r)[0]), "=r"((r)[1]), "=r"((r)[2]), "=r"((r)[3]) : "r"(a))
#define LDSM_X2(r, a) asm volatile( \
    "ldmatrix.sync.aligned.m8n8.x2.shared.b16 {%0,%1}, [%2];" \
    : "=r"((r)[0]), "=r"((r)[1]) : "r"(a))

__device__ __forceinline__ void mma_bf16(float* c, const uint32_t* a, const uint32_t* b) {
    asm volatile(
        "mma.sync.aligned.m16n8k16.row.col.f32.bf16.bf16.f32 "
        "{%0,%1,%2,%3}, {%4,%5,%6,%7}, {%8,%9}, {%0,%1,%2,%3};"
        : "+f"(c[0]), "+f"(c[1]), "+f"(c[2]), "+f"(c[3])
        : "r"(a[0]), "r"(a[1]), "r"(a[2]), "r"(a[3]), "r"(b[0]), "r"(b[1]));
}

// ---------------- degree / norm / CSR precompute ----------------
__global__ void k_deg_init(int n) {
    int i = blockIdx.x * blockDim.x + threadIdx.x;
    if (i < n) { g_deg[i] = 1.0f; g_cnt[i] = 0; }
}
__global__ void k_deg_edges(const int* __restrict__ ei, const float* __restrict__ w, int E) {
    int e = blockIdx.x * blockDim.x + threadIdx.x;
    if (e < E) {
        int c = ei[E + e];
        atomicAdd(&g_deg[c], w[e]);
        atomicAdd(&g_cnt[c], 1);
    }
}
__global__ void k_dinv(int n) {
    int i = blockIdx.x * blockDim.x + threadIdx.x;
    if (i < n) {
        float d = g_deg[i];
        g_dinv[i] = (d > 0.0f) ? rsqrtf(fmaxf(d, 1e-12f)) : 0.0f;
    }
}
__global__ void k_enorm(const int* __restrict__ ei, const float* __restrict__ w, int E) {
    int e = blockIdx.x * blockDim.x + threadIdx.x;
    if (e < E) g_enorm[e] = g_dinv[ei[e]] * w[e] * g_dinv[ei[E + e]];
}

// --- 3-kernel exclusive scan of g_cnt -> g_rstart ---
__global__ void k_scan1(int n) {
    __shared__ int sd[256];
    int t = threadIdx.x, i = blockIdx.x * 256 + t;
    int v = (i < n) ? g_cnt[i] : 0;
    sd[t] = v; __syncthreads();
#pragma unroll
    for (int off = 1; off < 256; off <<= 1) {
        int x = (t >= off) ? sd[t - off] : 0;
        __syncthreads();
        sd[t] += x;
        __syncthreads();
    }
    if (i < n) g_rstart[i] = sd[t] - v;      // exclusive within block
    if (t == 255) g_bsum[blockIdx.x] = sd[255];
}
__global__ void k_scan2(int nb) {
    __shared__ int sd[512];
    int t = threadIdx.x;
    int v = (t < nb) ? g_bsum[t] : 0;
    sd[t] = v; __syncthreads();
#pragma unroll
    for (int off = 1; off < 512; off <<= 1) {
        int x = (t >= off) ? sd[t - off] : 0;
        __syncthreads();
        sd[t] += x;
        __syncthreads();
    }
    if (t < nb) g_bsum[t] = sd[t] - v;       // exclusive
}
__global__ void k_scan3(int n, int E) {
    int i = blockIdx.x * blockDim.x + threadIdx.x;
    if (i < n) {
        int v = g_rstart[i] + g_bsum[i >> 8];
        g_rstart[i] = v;
        g_cursor[i] = v;
    }
    if (i == 0) g_rstart[n] = E;
}
__global__ void k_fill(const int* __restrict__ ei, int E) {
    int e = blockIdx.x * blockDim.x + threadIdx.x;
    if (e >= E) return;
    int pos = atomicAdd(&g_cursor[ei[E + e]], 1);
    g_csre[pos] = e;
}

// ---------------- weight transpose + bf16 split: Wt[n][k] ----------------
__global__ void k_wprep(const float* __restrict__ W, __nv_bfloat16* __restrict__ Hi,
                        __nv_bfloat16* __restrict__ Lo) {
    int i = blockIdx.x * blockDim.x + threadIdx.x;
    if (i >= 512 * 512) return;
    int k = i >> 9, n = i & 511;
    float x = W[i];
    __nv_bfloat16 h = __float2bfloat16(x);
    __nv_bfloat16 l = __float2bfloat16(x - __bfloat162float(h));
    Hi[n * 512 + k] = h;
    Lo[n * 512 + k] = l;
}

// ---------------- activation bf16 split ----------------
__global__ void k_asplit(const float4* __restrict__ X, __nv_bfloat16* __restrict__ Hi,
                         __nv_bfloat16* __restrict__ Lo, int n4) {
    int i = blockIdx.x * blockDim.x + threadIdx.x;
    if (i >= n4) return;
    float4 v = X[i];
    __nv_bfloat16 h0 = __float2bfloat16(v.x), h1 = __float2bfloat16(v.y);
    __nv_bfloat16 h2 = __float2bfloat16(v.z), h3 = __float2bfloat16(v.w);
    __nv_bfloat16 l0 = __float2bfloat16(v.x - __bfloat162float(h0));
    __nv_bfloat16 l1 = __float2bfloat16(v.y - __bfloat162float(h1));
    __nv_bfloat16 l2 = __float2bfloat16(v.z - __bfloat162float(h2));
    __nv_bfloat16 l3 = __float2bfloat16(v.w - __bfloat162float(h3));
    ((uint2*)Hi)[i] = make_uint2(pack2(h0, h1), pack2(h2, h3));
    ((uint2*)Lo)[i] = make_uint2(pack2(l0, l1), pack2(l2, l3));
}

// ---------------- mma.sync bf16-3x GEMM, 4-stage pipeline ----------------
#define PITCH   48
#define MAT_SZ  (128 * PITCH)
#define A_HI 0
#define A_LO (1 * MAT_SZ)
#define B_HI (2 * MAT_SZ)
#define B_LO (3 * MAT_SZ)
#define STAGE (4 * MAT_SZ)         // 24576
#define NSTG 4
#define GEMM_SMEM (NSTG * STAGE)   // 98304

__global__ __launch_bounds__(256, 2) void gemm_tc(
    const __nv_bfloat16* __restrict__ Ahi, const __nv_bfloat16* __restrict__ Alo,
    const __nv_bfloat16* __restrict__ Bhi, const __nv_bfloat16* __restrict__ Blo,
    float* __restrict__ hOut, int M) {
    extern __shared__ char smem[];
    const uint32_t sb = smem_u32(smem);
    const int tid = threadIdx.x, lane = tid & 31, wid = tid >> 5;
    const int bm = blockIdx.x * 128, bn = blockIdx.y * 128;

    const int sr = tid >> 1;
    const uint32_t sc = (uint32_t)(tid & 1) * 16;
    const bool av = (bm + sr) < M;
    const char* pAh = (const char*)Ahi + ((size_t)(bm + sr) * 512) * 2 + (tid & 1) * 16;
    const char* pAl = (const char*)Alo + ((size_t)(bm + sr) * 512) * 2 + (tid & 1) * 16;
    const char* pBh = (const char*)Bhi + ((size_t)(bn + sr) * 512) * 2 + (tid & 1) * 16;
    const char* pBl = (const char*)Blo + ((size_t)(bn + sr) * 512) * 2 + (tid & 1) * 16;
    const uint32_t so = (uint32_t)sr * PITCH + sc;

    auto do_stage = [&](int s) {
        const uint32_t bo = sb + (uint32_t)(s & 3) * STAGE;
        const size_t ko = (size_t)s * 32;
        cp16(bo + A_HI + so, pAh + ko, av);
        cp16(bo + A_LO + so, pAl + ko, av);
        cp16(bo + B_HI + so, pBh + ko, true);
        cp16(bo + B_LO + so, pBl + ko, true);
        CP_COMMIT();
    };

    const int wm = (wid >> 2) * 64;
    const int wn = (wid & 3) * 32;

    float acc[4][4][4];
#pragma unroll
    for (int i = 0; i < 4; i++)
#pragma unroll
        for (int j = 0; j < 4; j++)
#pragma unroll
            for (int k = 0; k < 4; k++) acc[i][j][k] = 0.0f;

    do_stage(0); do_stage(1); do_stage(2);

#pragma unroll 1
    for (int s = 0; s < 32; ++s) {
        if (s <= 29) CP_WAIT2();
        else if (s == 30) CP_WAIT1();
        else CP_WAIT0();
        __syncthreads();
        if (s + 3 < 32) do_stage(s + 3);

        const uint32_t bufb = sb + (uint32_t)(s & 3) * STAGE;
        uint32_t ah[4][4], al[4][4];
#pragma unroll
        for (int ma = 0; ma < 4; ++ma) {
            uint32_t aaddr = bufb + A_HI +
                (uint32_t)(wm + ma * 16 + (lane & 15)) * PITCH + ((lane >> 4) << 4);
            LDSM_X4(ah[ma], aaddr);
            LDSM_X4(al[ma], aaddr + (A_LO - A_HI));
        }
#pragma unroll
        for (int na = 0; na < 4; ++na) {
            uint32_t baddr = bufb + B_HI +
                (uint32_t)(wn + na * 8 + (lane & 7)) * PITCH + (((lane >> 3) & 1) << 4);
            uint32_t bh[2], bl[2];
            LDSM_X2(bh, baddr);
            LDSM_X2(bl, baddr + (B_LO - B_HI));
#pragma unroll
            for (int ma = 0; ma < 4; ++ma) {
                mma_bf16(acc[ma][na], ah[ma], bh);
                mma_bf16(acc[ma][na], al[ma], bh);
                mma_bf16(acc[ma][na], ah[ma], bl);
            }
        }
    }

#pragma unroll
    for (int ma = 0; ma < 4; ++ma) {
        int r0 = bm + wm + ma * 16 + (lane >> 2);
        int r1 = r0 + 8;
#pragma unroll
        for (int na = 0; na < 4; ++na) {
            int col = bn + wn + na * 8 + 2 * (lane & 3);
            float* c = acc[ma][na];
            if (r0 < M) *(float2*)&hOut[(size_t)r0 * 512 + col] = make_float2(c[0], c[1]);
            if (r1 < M) *(float2*)&hOut[(size_t)r1 * 512 + col] = make_float2(c[2], c[3]);
        }
    }
}

// ---------------- fused gather + epilogue ----------------
// per node: agg = dinv^2*h[node] + sum_in nm*h[row]; then bias/relu/L2norm/residual
// NOTE: out must NOT alias h (neighbor rows of h are read by other blocks).
// out MAY alias resid (only own-row read, before own-row write).
__global__ __launch_bounds__(128) void k_gather_epi(
    const float* __restrict__ h, const float* __restrict__ bias,
    const float* __restrict__ resid, float* __restrict__ out,
    __nv_bfloat16* __restrict__ hi, __nv_bfloat16* __restrict__ lo,
    const int* __restrict__ ei, int E, int n) {
    int node = blockIdx.x;
    if (node >= n) return;
    int tid = threadIdx.x;

    float dv = g_dinv[node];
    float d2 = dv * dv;
    const float4* h4 = (const float4*)h;
    float4 v = h4[(size_t)node * 128 + tid];
    float4 acc = make_float4(v.x * d2, v.y * d2, v.z * d2, v.w * d2);

    int beg = g_rstart[node], end = g_rstart[node + 1];
    for (int j = beg; j < end; ++j) {
        int e = g_csre[j];
        float nm = g_enorm[e];
        int r = ei[e];
        float4 hv = h4[(size_t)r * 128 + tid];
        acc.x += nm * hv.x; acc.y += nm * hv.y;
        acc.z += nm * hv.z; acc.w += nm * hv.w;
    }

    float4 b = ((const float4*)bias)[tid];
    acc.x = fmaxf(acc.x + b.x, 0.0f);
    acc.y = fmaxf(acc.y + b.y, 0.0f);
    acc.z = fmaxf(acc.z + b.z, 0.0f);
    acc.w = fmaxf(acc.w + b.w, 0.0f);

    float s = acc.x * acc.x + acc.y * acc.y + acc.z * acc.z + acc.w * acc.w;
#pragma unroll
    for (int off = 16; off > 0; off >>= 1)
        s += __shfl_down_sync(0xFFFFFFFFu, s, off);

    __shared__ float warp_s[4];
    __shared__ float s_total;
    if ((tid & 31) == 0) warp_s[tid >> 5] = s;
    __syncthreads();
    if (tid == 0) s_total = warp_s[0] + warp_s[1] + warp_s[2] + warp_s[3];
    __syncthreads();

    float inv = 0.5f / fmaxf(sqrtf(s_total), 1e-12f);
    float4 r = ((const float4*)(resid + (size_t)node * 512))[tid];
    float4 o = make_float4(acc.x * inv + r.x * 0.5f, acc.y * inv + r.y * 0.5f,
                           acc.z * inv + r.z * 0.5f, acc.w * inv + r.w * 0.5f);
    ((float4*)(out + (size_t)node * 512))[tid] = o;
    if (hi) {
        __nv_bfloat16 h0 = __float2bfloat16(o.x), h1 = __float2bfloat16(o.y);
        __nv_bfloat16 h2 = __float2bfloat16(o.z), h3 = __float2bfloat16(o.w);
        __nv_bfloat16 l0 = __float2bfloat16(o.x - __bfloat162float(h0));
        __nv_bfloat16 l1 = __float2bfloat16(o.y - __bfloat162float(h1));
        __nv_bfloat16 l2 = __float2bfloat16(o.z - __bfloat162float(h2));
        __nv_bfloat16 l3 = __float2bfloat16(o.w - __bfloat162float(h3));
        size_t idx = (size_t)node * 128 + tid;
        ((uint2*)hi)[idx] = make_uint2(pack2(h0, h1), pack2(h2, h3));
        ((uint2*)lo)[idx] = make_uint2(pack2(l0, l1), pack2(l2, l3));
    }
}

// ---------------- final projection: p[i,0:2] = h[i,:] @ Wf ----------------
__global__ __launch_bounds__(256) void k_pdot(const float* __restrict__ h,
                                              const float* __restrict__ Wf, int n) {
    __shared__ float sWf[1024];
    int tid = threadIdx.x;
#pragma unroll
    for (int i = tid; i < 1024; i += 256) sWf[i] = Wf[i];
    __syncthreads();

    int node = blockIdx.x * 8 + (tid >> 5);
    if (node >= n) return;
    int lane = tid & 31;
    const float* hr = h + (size_t)node * 512;
    float s0 = 0.f, s1 = 0.f;
#pragma unroll
    for (int j = 0; j < 16; j++) {
        int k = lane + j * 32;
        float hv = hr[k];
        s0 += hv * sWf[k * 2];
        s1 += hv * sWf[k * 2 + 1];
    }
#pragma unroll
    for (int off = 16; off > 0; off >>= 1) {
        s0 += __shfl_down_sync(0xFFFFFFFFu, s0, off);
        s1 += __shfl_down_sync(0xFFFFFFFFu, s1, off);
    }
    if (lane == 0) {
        g_p[node * 2]     = s0;
        g_p[node * 2 + 1] = s1;
    }
}

// fused CSR gather + log_softmax for the 2-wide final conv
__global__ void k_pgather_lsm(const int* __restrict__ ei, const float* __restrict__ bf,
                              int E, int n) {
    int i = blockIdx.x * blockDim.x + threadIdx.x;
    if (i >= n) return;
    float dv = g_dinv[i];
    float d2 = dv * dv;
    float a0 = d2 * g_p[i * 2], a1 = d2 * g_p[i * 2 + 1];
    int beg = g_rstart[i], end = g_rstart[i + 1];
    for (int j = beg; j < end; ++j) {
        int e = g_csre[j];
        float nm = g_enorm[e];
        int r = ei[e];
        a0 += nm * g_p[r * 2];
        a1 += nm * g_p[r * 2 + 1];
    }
    float z0 = a0 + bf[0], z1 = a1 + bf[1];
    float m = fmaxf(z0, z1);
    float lse = m + logf(expf(z0 - m) + expf(z1 - m));
    g_ls[i * 2]     = z0 - lse;
    g_ls[i * 2 + 1] = z1 - lse;
}

__global__ void k_pred(const int* __restrict__ pe, float* __restrict__ out, int NP) {
    int p = blockIdx.x * blockDim.x + threadIdx.x;
    if (p >= NP) return;
    int u = pe[p], v = pe[NP + p];
    out[p * 2]     = -(g_ls[u * 2]     * g_ls[v * 2]);
    out[p * 2 + 1] = -(g_ls[u * 2 + 1] * g_ls[v * 2 + 1]);
}

// ---------------- launch ----------------
extern "C" void kernel_launch(void* const* d_in, const int* in_sizes, int n_in,
                              void* d_out, int out_size) {
    const float* x   = (const float*)d_in[0];
    const int*   ei  = (const int*)d_in[1];
    const float* w   = (const float*)d_in[2];
    const int*   pe  = (const int*)d_in[3];
    const float* W1  = (const float*)d_in[4];
    const float* b1  = (const float*)d_in[5];
    const float* W2  = (const float*)d_in[6];
    const float* b2  = (const float*)d_in[7];
    const float* Wf  = (const float*)d_in[8];
    const float* bf  = (const float*)d_in[9];
    float* out = (float*)d_out;

    const int N  = in_sizes[0] / DDIM;
    const int E  = in_sizes[2];
    const int NP = in_sizes[3] / 2;
    const int NB = (N + 255) / 256;       // scan blocks (<=512)

    float *hbuf, *x1buf;
    __nv_bfloat16 *ahi, *alo, *w1h, *w1l, *w2h, *w2l;
    cudaGetSymbolAddress((void**)&hbuf,  g_h);
    cudaGetSymbolAddress((void**)&x1buf, g_x1);
    cudaGetSymbolAddress((void**)&ahi, g_Ahi);
    cudaGetSymbolAddress((void**)&alo, g_Alo);
    cudaGetSymbolAddress((void**)&w1h, g_W1h);
    cudaGetSymbolAddress((void**)&w1l, g_W1l);
    cudaGetSymbolAddress((void**)&w2h, g_W2h);
    cudaGetSymbolAddress((void**)&w2l, g_W2l);

    cudaFuncSetAttribute(gemm_tc, cudaFuncAttributeMaxDynamicSharedMemorySize,
                         GEMM_SMEM);

    dim3 ggrid((N + 127) / 128, 4);
    const int n4 = N * (DDIM / 4);

    // precompute: degree/norm + CSR + weight/act splits
    k_deg_init <<<NB, 256>>>(N);
    k_deg_edges<<<(E + 255) / 256, 256>>>(ei, w, E);
    k_dinv     <<<NB, 256>>>(N);
    k_enorm    <<<(E + 255) / 256, 256>>>(ei, w, E);
    k_scan1    <<<NB, 256>>>(N);
    k_scan2    <<<1, 512>>>(NB);
    k_scan3    <<<NB, 256>>>(N, E);
    k_fill     <<<(E + 255) / 256, 256>>>(ei, E);
    k_wprep    <<<(512 * 512 + 255) / 256, 256>>>(W1, w1h, w1l);
    k_wprep    <<<(512 * 512 + 255) / 256, 256>>>(W2, w2h, w2l);
    k_asplit   <<<(n4 + 255) / 256, 256>>>((const float4*)x, ahi, alo, n4);

    // ---- layer 1: gemm -> hbuf; gather reads hbuf, writes x1buf (+ bf16 split)
    gemm_tc     <<<ggrid, 256, GEMM_SMEM>>>(ahi, alo, w1h, w1l, hbuf, N);
    k_gather_epi<<<N, 128>>>(hbuf, b1, x, x1buf, ahi, alo, ei, E, N);

    // ---- layer 2: gemm -> hbuf; gather reads hbuf, resid x1buf, writes x1buf
    // (out aliases resid: own-row only — safe; must NOT alias h)
    gemm_tc     <<<ggrid, 256, GEMM_SMEM>>>(ahi, alo, w2h, w2l, hbuf, N);
    k_gather_epi<<<N, 128>>>(hbuf, b2, x1buf, x1buf,
                             (__nv_bfloat16*)0, (__nv_bfloat16*)0, ei, E, N);

    // ---- final conv (512 -> 2) + log_softmax ----
    k_pdot       <<<(N + 7) / 8, 256>>>(x1buf, Wf, N);
    k_pgather_lsm<<<NB, 256>>>(ei, bf, E, N);

    // ---- predictor edges ----
    k_pred<<<(NP + 255) / 256, 256>>>(pe, out, NP);
}

// round 12
// speedup vs baseline: 2.6015x; 1.2557x over previous
#include <cuda_runtime.h>
#include <cuda_fp16.h>
#include <math.h>
#include <stdint.h>

#define NNODES 100000
#define NEDGES 150000
#define NPRED  200000
#define DDIM   512

// ---------------- scratch (no allocs allowed) ----------------
__device__ float g_h  [(size_t)NNODES * DDIM];
__device__ float g_x1 [(size_t)NNODES * DDIM];
__device__ __half g_Ahi[(size_t)NNODES * DDIM];
__device__ __half g_Alo[(size_t)NNODES * DDIM];
__device__ __half g_W1t[512 * 512];
__device__ __half g_W2t[512 * 512];
__device__ float g_deg [NNODES];
__device__ float g_dinv[NNODES];
__device__ float g_enorm[NEDGES];
__device__ float g_p   [NNODES * 2];
__device__ float g_ls  [NNODES * 2];
// CSR (edges grouped by destination col)
__device__ int g_cnt   [NNODES];
__device__ int g_rstart[NNODES + 1];
__device__ int g_cursor[NNODES];
__device__ int g_csre  [NEDGES];
__device__ int g_bsum  [512];

// ---------------- helpers ----------------
__device__ __forceinline__ uint32_t smem_u32(const void* p) {
    uint32_t a;
    asm("{ .reg .u64 t; cvta.to.shared.u64 t, %1; cvt.u32.u64 %0, t; }" : "=r"(a) : "l"(p));
    return a;
}
__device__ __forceinline__ uint32_t pack2h(__half a, __half b) {
    return (uint32_t)__half_as_ushort(a) | ((uint32_t)__half_as_ushort(b) << 16);
}
__device__ __forceinline__ void cp16(uint32_t dst, const void* src, bool p) {
    asm volatile("cp.async.cg.shared.global [%0], [%1], 16, %2;"
                 :: "r"(dst), "l"(src), "r"(p ? 16 : 0) : "memory");
}
#define CP_COMMIT() asm volatile("cp.async.commit_group;" ::: "memory")
#define CP_WAIT2()  asm volatile("cp.async.wait_group 2;" ::: "memory")
#define CP_WAIT1()  asm volatile("cp.async.wait_group 1;" ::: "memory")
#define CP_WAIT0()  asm volatile("cp.async.wait_group 0;" ::: "memory")
#define LDSM_X4(r, a) asm volatile( \
    "ldmatrix.sync.aligned.m8n8.x4.shared.b16 {%0,%1,%2,%3}, [%4];" \
    : "=r"((r)[0]), "=r"((r)[1]), "=r"((r)[2]), "=r"((r)[3]) : "r"(a))
#define LDSM_X2(r, a) asm volatile( \
    "ldmatrix.sync.aligned.m8n8.x2.shared.b16 {%0,%1}, [%2];" \
    : "=r"((r)[0]), "=r"((r)[1]) : "r"(a))

__device__ __forceinline__ void mma_f16(float* c, const uint32_t* a, const uint32_t* b) {
    asm volatile(
        "mma.sync.aligned.m16n8k16.row.col.f32.f16.f16.f32 "
        "{%0,%1,%2,%3}, {%4,%5,%6,%7}, {%8,%9}, {%0,%1,%2,%3};"
        : "+f"(c[0]), "+f"(c[1]), "+f"(c[2]), "+f"(c[3])
        : "r"(a[0]), "r"(a[1]), "r"(a[2]), "r"(a[3]), "r"(b[0]), "r"(b[1]));
}

// ---------------- degree / norm / CSR precompute ----------------
__global__ void k_deg_init(int n) {
    int i = blockIdx.x * blockDim.x + threadIdx.x;
    if (i < n) { g_deg[i] = 1.0f; g_cnt[i] = 0; }
}
__global__ void k_deg_edges(const int* __restrict__ ei, const float* __restrict__ w, int E) {
    int e = blockIdx.x * blockDim.x + threadIdx.x;
    if (e < E) {
        int c = ei[E + e];
        atomicAdd(&g_deg[c], w[e]);
        atomicAdd(&g_cnt[c], 1);
    }
}
__global__ void k_dinv(int n) {
    int i = blockIdx.x * blockDim.x + threadIdx.x;
    if (i < n) {
        float d = g_deg[i];
        g_dinv[i] = (d > 0.0f) ? rsqrtf(fmaxf(d, 1e-12f)) : 0.0f;
    }
}
__global__ void k_enorm(const int* __restrict__ ei, const float* __restrict__ w, int E) {
    int e = blockIdx.x * blockDim.x + threadIdx.x;
    if (e < E) g_enorm[e] = g_dinv[ei[e]] * w[e] * g_dinv[ei[E + e]];
}

// --- 3-kernel exclusive scan of g_cnt -> g_rstart ---
__global__ void k_scan1(int n) {
    __shared__ int sd[256];
    int t = threadIdx.x, i = blockIdx.x * 256 + t;
    int v = (i < n) ? g_cnt[i] : 0;
    sd[t] = v; __syncthreads();
#pragma unroll
    for (int off = 1; off < 256; off <<= 1) {
        int x = (t >= off) ? sd[t - off] : 0;
        __syncthreads();
        sd[t] += x;
        __syncthreads();
    }
    if (i < n) g_rstart[i] = sd[t] - v;
    if (t == 255) g_bsum[blockIdx.x] = sd[255];
}
__global__ void k_scan2(int nb) {
    __shared__ int sd[512];
    int t = threadIdx.x;
    int v = (t < nb) ? g_bsum[t] : 0;
    sd[t] = v; __syncthreads();
#pragma unroll
    for (int off = 1; off < 512; off <<= 1) {
        int x = (t >= off) ? sd[t - off] : 0;
        __syncthreads();
        sd[t] += x;
        __syncthreads();
    }
    if (t < nb) g_bsum[t] = sd[t] - v;
}
__global__ void k_scan3(int n, int E) {
    int i = blockIdx.x * blockDim.x + threadIdx.x;
    if (i < n) {
        int v = g_rstart[i] + g_bsum[i >> 8];
        g_rstart[i] = v;
        g_cursor[i] = v;
    }
    if (i == 0) g_rstart[n] = E;
}
__global__ void k_fill(const int* __restrict__ ei, int E) {
    int e = blockIdx.x * blockDim.x + threadIdx.x;
    if (e >= E) return;
    int pos = atomicAdd(&g_cursor[ei[E + e]], 1);
    g_csre[pos] = e;
}

// ---------------- weight transpose + fp16 round: Wt[n][k] ----------------
__global__ void k_wprep(const float* __restrict__ W, __half* __restrict__ Wt) {
    int i = blockIdx.x * blockDim.x + threadIdx.x;
    if (i >= 512 * 512) return;
    int k = i >> 9, n = i & 511;
    Wt[n * 512 + k] = __float2half_rn(W[i]);
}

// ---------------- activation fp16 hi/lo split ----------------
__global__ void k_asplit(const float4* __restrict__ X, __half* __restrict__ Hi,
                         __half* __restrict__ Lo, int n4) {
    int i = blockIdx.x * blockDim.x + threadIdx.x;
    if (i >= n4) return;
    float4 v = X[i];
    __half h0 = __float2half_rn(v.x), h1 = __float2half_rn(v.y);
    __half h2 = __float2half_rn(v.z), h3 = __float2half_rn(v.w);
    __half l0 = __float2half_rn(v.x - __half2float(h0));
    __half l1 = __float2half_rn(v.y - __half2float(h1));
    __half l2 = __float2half_rn(v.z - __half2float(h2));
    __half l3 = __float2half_rn(v.w - __half2float(h3));
    ((uint2*)Hi)[i] = make_uint2(pack2h(h0, h1), pack2h(h2, h3));
    ((uint2*)Lo)[i] = make_uint2(pack2h(l0, l1), pack2h(l2, l3));
}

// ---------------- mma.sync fp16 2-pass GEMM, 4-stage pipeline ----------------
// C[M,512] = (Ahi+Alo)[M,512] @ Bh ; B = Wt[n][k] fp16 (rounded once).
// CTA tile 128x128, K step 16, 4-stage cp.async ring, one barrier per step.
// Stage = 3 matrices x 128 rows x 48B pitch = 18KB; 4 stages = 72KB; 2 CTA/SM.
#define PITCH   48
#define MAT_SZ  (128 * PITCH)
#define A_HI 0
#define A_LO (1 * MAT_SZ)
#define B_OF (2 * MAT_SZ)
#define STAGE (3 * MAT_SZ)         // 18432
#define NSTG 4
#define GEMM_SMEM (NSTG * STAGE)   // 73728

__global__ __launch_bounds__(256, 2) void gemm_tc(
    const __half* __restrict__ Ahi, const __half* __restrict__ Alo,
    const __half* __restrict__ Bt, float* __restrict__ hOut, int M) {
    extern __shared__ char smem[];
    const uint32_t sb = smem_u32(smem);
    const int tid = threadIdx.x, lane = tid & 31, wid = tid >> 5;
    const int bm = blockIdx.x * 128, bn = blockIdx.y * 128;

    const int sr = tid >> 1;
    const bool av = (bm + sr) < M;
    const char* pAh = (const char*)Ahi + ((size_t)(bm + sr) * 512) * 2 + (tid & 1) * 16;
    const char* pAl = (const char*)Alo + ((size_t)(bm + sr) * 512) * 2 + (tid & 1) * 16;
    const char* pB  = (const char*)Bt  + ((size_t)(bn + sr) * 512) * 2 + (tid & 1) * 16;
    const uint32_t so = (uint32_t)sr * PITCH + (uint32_t)(tid & 1) * 16;

    auto do_stage = [&](int s) {
        const uint32_t bo = sb + (uint32_t)(s & 3) * STAGE;
        const size_t ko = (size_t)s * 32;
        cp16(bo + A_HI + so, pAh + ko, av);
        cp16(bo + A_LO + so, pAl + ko, av);
        cp16(bo + B_OF + so, pB  + ko, true);
        CP_COMMIT();
    };

    const int wm = (wid >> 2) * 64;
    const int wn = (wid & 3) * 32;

    float acc[4][4][4];
#pragma unroll
    for (int i = 0; i < 4; i++)
#pragma unroll
        for (int j = 0; j < 4; j++)
#pragma unroll
            for (int k = 0; k < 4; k++) acc[i][j][k] = 0.0f;

    do_stage(0); do_stage(1); do_stage(2);

#pragma unroll 1
    for (int s = 0; s < 32; ++s) {
        if (s <= 29) CP_WAIT2();
        else if (s == 30) CP_WAIT1();
        else CP_WAIT0();
        __syncthreads();
        if (s + 3 < 32) do_stage(s + 3);

        const uint32_t bufb = sb + (uint32_t)(s & 3) * STAGE;
        uint32_t ah[4][4], al[4][4];
#pragma unroll
        for (int ma = 0; ma < 4; ++ma) {
            uint32_t aaddr = bufb + A_HI +
                (uint32_t)(wm + ma * 16 + (lane & 15)) * PITCH + ((lane >> 4) << 4);
            LDSM_X4(ah[ma], aaddr);
            LDSM_X4(al[ma], aaddr + (A_LO - A_HI));
        }
#pragma unroll
        for (int na = 0; na < 4; ++na) {
            uint32_t baddr = bufb + B_OF +
                (uint32_t)(wn + na * 8 + (lane & 7)) * PITCH + (((lane >> 3) & 1) << 4);
            uint32_t bh[2];
            LDSM_X2(bh, baddr);
#pragma unroll
            for (int ma = 0; ma < 4; ++ma) {
                mma_f16(acc[ma][na], ah[ma], bh);
                mma_f16(acc[ma][na], al[ma], bh);
            }
        }
    }

#pragma unroll
    for (int ma = 0; ma < 4; ++ma) {
        int r0 = bm + wm + ma * 16 + (lane >> 2);
        int r1 = r0 + 8;
#pragma unroll
        for (int na = 0; na < 4; ++na) {
            int col = bn + wn + na * 8 + 2 * (lane & 3);
            float* c = acc[ma][na];
            if (r0 < M) *(float2*)&hOut[(size_t)r0 * 512 + col] = make_float2(c[0], c[1]);
            if (r1 < M) *(float2*)&hOut[(size_t)r1 * 512 + col] = make_float2(c[2], c[3]);
        }
    }
}

// ---------------- fused gather + epilogue (+ optional split / projection) ---
// per node: agg = dinv^2*h[node] + sum_in nm*h[row]; bias/relu/L2norm/residual.
// out must NOT alias h; out MAY alias resid (own-row only).
// If hi != 0: write fp16 hi/lo split of o. If Wf != 0: write p = o @ Wf (512->2).
__global__ __launch_bounds__(128) void k_gather_epi(
    const float* __restrict__ h, const float* __restrict__ bias,
    const float* __restrict__ resid, float* __restrict__ out,
    __half* __restrict__ hi, __half* __restrict__ lo,
    const float* __restrict__ Wf,
    const int* __restrict__ ei, int E, int n) {
    int node = blockIdx.x;
    if (node >= n) return;
    int tid = threadIdx.x;

    float dv = g_dinv[node];
    float d2 = dv * dv;
    const float4* h4 = (const float4*)h;
    float4 v = h4[(size_t)node * 128 + tid];
    float4 acc = make_float4(v.x * d2, v.y * d2, v.z * d2, v.w * d2);

    int beg = g_rstart[node], end = g_rstart[node + 1];
    for (int j = beg; j < end; ++j) {
        int e = g_csre[j];
        float nm = g_enorm[e];
        int r = ei[e];
        float4 hv = h4[(size_t)r * 128 + tid];
        acc.x += nm * hv.x; acc.y += nm * hv.y;
        acc.z += nm * hv.z; acc.w += nm * hv.w;
    }

    float4 b = ((const float4*)bias)[tid];
    acc.x = fmaxf(acc.x + b.x, 0.0f);
    acc.y = fmaxf(acc.y + b.y, 0.0f);
    acc.z = fmaxf(acc.z + b.z, 0.0f);
    acc.w = fmaxf(acc.w + b.w, 0.0f);

    float s = acc.x * acc.x + acc.y * acc.y + acc.z * acc.z + acc.w * acc.w;
#pragma unroll
    for (int off = 16; off > 0; off >>= 1)
        s += __shfl_down_sync(0xFFFFFFFFu, s, off);

    __shared__ float warp_s[4];
    __shared__ float s_total;
    if ((tid & 31) == 0) warp_s[tid >> 5] = s;
    __syncthreads();
    if (tid == 0) s_total = warp_s[0] + warp_s[1] + warp_s[2] + warp_s[3];
    __syncthreads();

    float inv = 0.5f / fmaxf(sqrtf(s_total), 1e-12f);
    float4 r = ((const float4*)(resid + (size_t)node * 512))[tid];
    float4 o = make_float4(acc.x * inv + r.x * 0.5f, acc.y * inv + r.y * 0.5f,
                           acc.z * inv + r.z * 0.5f, acc.w * inv + r.w * 0.5f);
    ((float4*)(out + (size_t)node * 512))[tid] = o;

    if (hi) {
        __half h0 = __float2half_rn(o.x), h1 = __float2half_rn(o.y);
        __half h2 = __float2half_rn(o.z), h3 = __float2half_rn(o.w);
        __half l0 = __float2half_rn(o.x - __half2float(h0));
        __half l1 = __float2half_rn(o.y - __half2float(h1));
        __half l2 = __float2half_rn(o.z - __half2float(h2));
        __half l3 = __float2half_rn(o.w - __half2float(h3));
        size_t idx = (size_t)node * 128 + tid;
        ((uint2*)hi)[idx] = make_uint2(pack2h(h0, h1), pack2h(h2, h3));
        ((uint2*)lo)[idx] = make_uint2(pack2h(l0, l1), pack2h(l2, l3));
    }

    if (Wf) {
        // p[node][j] = sum_k o_k * Wf[k][j], j=0,1 ; Wf row-major [512][2]
        float4 w0 = ((const float4*)Wf)[tid * 2];
        float4 w1 = ((const float4*)Wf)[tid * 2 + 1];
        float s0 = o.x * w0.x + o.y * w0.z + o.z * w1.x + o.w * w1.z;
        float s1 = o.x * w0.y + o.y * w0.w + o.z * w1.y + o.w * w1.w;
#pragma unroll
        for (int off = 16; off > 0; off >>= 1) {
            s0 += __shfl_down_sync(0xFFFFFFFFu, s0, off);
            s1 += __shfl_down_sync(0xFFFFFFFFu, s1, off);
        }
        __shared__ float ws0[4], ws1[4];
        if ((tid & 31) == 0) { ws0[tid >> 5] = s0; ws1[tid >> 5] = s1; }
        __syncthreads();
        if (tid == 0) {
            g_p[node * 2]     = ws0[0] + ws0[1] + ws0[2] + ws0[3];
            g_p[node * 2 + 1] = ws1[0] + ws1[1] + ws1[2] + ws1[3];
        }
    }
}

// fused CSR gather + log_softmax for the 2-wide final conv
__global__ void k_pgather_lsm(const int* __restrict__ ei, const float* __restrict__ bf,
                              int E, int n) {
    int i = blockIdx.x * blockDim.x + threadIdx.x;
    if (i >= n) return;
    float dv = g_dinv[i];
    float d2 = dv * dv;
    float a0 = d2 * g_p[i * 2], a1 = d2 * g_p[i * 2 + 1];
    int beg = g_rstart[i], end = g_rstart[i + 1];
    for (int j = beg; j < end; ++j) {
        int e = g_csre[j];
        float nm = g_enorm[e];
        int r = ei[e];
        a0 += nm * g_p[r * 2];
        a1 += nm * g_p[r * 2 + 1];
    }
    float z0 = a0 + bf[0], z1 = a1 + bf[1];
    float m = fmaxf(z0, z1);
    float lse = m + logf(expf(z0 - m) + expf(z1 - m));
    g_ls[i * 2]     = z0 - lse;
    g_ls[i * 2 + 1] = z1 - lse;
}

__global__ void k_pred(const int* __restrict__ pe, float* __restrict__ out, int NP) {
    int p = blockIdx.x * blockDim.x + threadIdx.x;
    if (p >= NP) return;
    int u = pe[p], v = pe[NP + p];
    out[p * 2]     = -(g_ls[u * 2]     * g_ls[v * 2]);
    out[p * 2 + 1] = -(g_ls[u * 2 + 1] * g_ls[v * 2 + 1]);
}

// ---------------- launch ----------------
extern "C" void kernel_launch(void* const* d_in, const int* in_sizes, int n_in,
                              void* d_out, int out_size) {
    const float* x   = (const float*)d_in[0];
    const int*   ei  = (const int*)d_in[1];
    const float* w   = (const float*)d_in[2];
    const int*   pe  = (const int*)d_in[3];
    const float* W1  = (const float*)d_in[4];
    const float* b1  = (const float*)d_in[5];
    const float* W2  = (const float*)d_in[6];
    const float* b2  = (const float*)d_in[7];
    const float* Wf  = (const float*)d_in[8];
    const float* bf  = (const float*)d_in[9];
    float* out = (float*)d_out;

    const int N  = in_sizes[0] / DDIM;
    const int E  = in_sizes[2];
    const int NP = in_sizes[3] / 2;
    const int NB = (N + 255) / 256;

    float *hbuf, *x1buf;
    __half *ahi, *alo, *w1t, *w2t;
    cudaGetSymbolAddress((void**)&hbuf,  g_h);
    cudaGetSymbolAddress((void**)&x1buf, g_x1);
    cudaGetSymbolAddress((void**)&ahi, g_Ahi);
    cudaGetSymbolAddress((void**)&alo, g_Alo);
    cudaGetSymbolAddress((void**)&w1t, g_W1t);
    cudaGetSymbolAddress((void**)&w2t, g_W2t);

    cudaFuncSetAttribute(gemm_tc, cudaFuncAttributeMaxDynamicSharedMemorySize,
                         GEMM_SMEM);

    dim3 ggrid((N + 127) / 128, 4);
    const int n4 = N * (DDIM / 4);

    // precompute: degree/norm + CSR + weight round / act split
    k_deg_init <<<NB, 256>>>(N);
    k_deg_edges<<<(E + 255) / 256, 256>>>(ei, w, E);
    k_dinv     <<<NB, 256>>>(N);
    k_enorm    <<<(E + 255) / 256, 256>>>(ei, w, E);
    k_scan1    <<<NB, 256>>>(N);
    k_scan2    <<<1, 512>>>(NB);
    k_scan3    <<<NB, 256>>>(N, E);
    k_fill     <<<(E + 255) / 256, 256>>>(ei, E);
    k_wprep    <<<(512 * 512 + 255) / 256, 256>>>(W1, w1t);
    k_wprep    <<<(512 * 512 + 255) / 256, 256>>>(W2, w2t);
    k_asplit   <<<(n4 + 255) / 256, 256>>>((const float4*)x, ahi, alo, n4);

    // ---- layer 1: gemm -> hbuf; gather reads hbuf, writes x1buf + fp16 split
    gemm_tc     <<<ggrid, 256, GEMM_SMEM>>>(ahi, alo, w1t, hbuf, N);
    k_gather_epi<<<N, 128>>>(hbuf, b1, x, x1buf, ahi, alo, (const float*)0,
                             ei, E, N);

    // ---- layer 2: gemm -> hbuf; gather reads hbuf, resid x1buf, writes x1buf
    //      + fused 512->2 projection into g_p
    gemm_tc     <<<ggrid, 256, GEMM_SMEM>>>(ahi, alo, w2t, hbuf, N);
    k_gather_epi<<<N, 128>>>(hbuf, b2, x1buf, x1buf,
                             (__half*)0, (__half*)0, Wf, ei, E, N);

    // ---- final conv scatter + log_softmax ----
    k_pgather_lsm<<<NB, 256>>>(ei, bf, E, N);

    // ---- predictor edges ----
    k_pred<<<(NP + 255) / 256, 256>>>(pe, out, NP);
}

// round 16
// speedup vs baseline: 3.5560x; 1.3669x over previous
#include <cuda_runtime.h>
#include <cuda_fp16.h>
#include <math.h>
#include <stdint.h>

#define NNODES 100000
#define NEDGES 150000
#define NPRED  200000
#define DDIM   512

// ---------------- scratch (no allocs allowed) ----------------
__device__ float g_h  [(size_t)NNODES * DDIM];
__device__ float g_x1 [(size_t)NNODES * DDIM];
__device__ __half g_Af [(size_t)NNODES * DDIM];
__device__ __half g_W1t[512 * 512];
__device__ __half g_W2t[512 * 512];
__device__ float g_deg [NNODES];
__device__ float g_dinv[NNODES];
__device__ float g_enorm[NEDGES];
__device__ float g_p   [NNODES * 2];
__device__ float g_ls  [NNODES * 2];
// CSR (edges grouped by destination col)
__device__ int g_cnt   [NNODES];
__device__ int g_rstart[NNODES + 1];
__device__ int g_cursor[NNODES];
__device__ int g_csre  [NEDGES];
__device__ int g_bsum  [512];

// ---------------- helpers ----------------
__device__ __forceinline__ uint32_t smem_u32(const void* p) {
    uint32_t a;
    asm("{ .reg .u64 t; cvta.to.shared.u64 t, %1; cvt.u32.u64 %0, t; }" : "=r"(a) : "l"(p));
    return a;
}
__device__ __forceinline__ uint32_t pack2h(__half a, __half b) {
    return (uint32_t)__half_as_ushort(a) | ((uint32_t)__half_as_ushort(b) << 16);
}
__device__ __forceinline__ void cp16(uint32_t dst, const void* src, bool p) {
    asm volatile("cp.async.cg.shared.global [%0], [%1], 16, %2;"
                 :: "r"(dst), "l"(src), "r"(p ? 16 : 0) : "memory");
}
#define CP_COMMIT() asm volatile("cp.async.commit_group;" ::: "memory")
#define CP_WAIT2()  asm volatile("cp.async.wait_group 2;" ::: "memory")
#define CP_WAIT1()  asm volatile("cp.async.wait_group 1;" ::: "memory")
#define CP_WAIT0()  asm volatile("cp.async.wait_group 0;" ::: "memory")
#define LDSM_X4(r, a) asm volatile( \
    "ldmatrix.sync.aligned.m8n8.x4.shared.b16 {%0,%1,%2,%3}, [%4];" \
    : "=r"((r)[0]), "=r"((r)[1]), "=r"((r)[2]), "=r"((r)[3]) : "r"(a))
#define LDSM_X2(r, a) asm volatile( \
    "ldmatrix.sync.aligned.m8n8.x2.shared.b16 {%0,%1}, [%2];" \
    : "=r"((r)[0]), "=r"((r)[1]) : "r"(a))

__device__ __forceinline__ void mma_f16(float* c, const uint32_t* a, const uint32_t* b) {
    asm volatile(
        "mma.sync.aligned.m16n8k16.row.col.f32.f16.f16.f32 "
        "{%0,%1,%2,%3}, {%4,%5,%6,%7}, {%8,%9}, {%0,%1,%2,%3};"
        : "+f"(c[0]), "+f"(c[1]), "+f"(c[2]), "+f"(c[3])
        : "r"(a[0]), "r"(a[1]), "r"(a[2]), "r"(a[3]), "r"(b[0]), "r"(b[1]));
}

// ---------------- degree / norm / CSR precompute ----------------
__global__ void k_deg_init(int n) {
    int i = blockIdx.x * blockDim.x + threadIdx.x;
    if (i < n) { g_deg[i] = 1.0f; g_cnt[i] = 0; }
}
__global__ void k_deg_edges(const int* __restrict__ ei, const float* __restrict__ w, int E) {
    int e = blockIdx.x * blockDim.x + threadIdx.x;
    if (e < E) {
        int c = ei[E + e];
        atomicAdd(&g_deg[c], w[e]);
        atomicAdd(&g_cnt[c], 1);
    }
}
__global__ void k_dinv(int n) {
    int i = blockIdx.x * blockDim.x + threadIdx.x;
    if (i < n) {
        float d = g_deg[i];
        g_dinv[i] = (d > 0.0f) ? rsqrtf(fmaxf(d, 1e-12f)) : 0.0f;
    }
}
__global__ void k_enorm(const int* __restrict__ ei, const float* __restrict__ w, int E) {
    int e = blockIdx.x * blockDim.x + threadIdx.x;
    if (e < E) g_enorm[e] = g_dinv[ei[e]] * w[e] * g_dinv[ei[E + e]];
}

// --- 3-kernel exclusive scan of g_cnt -> g_rstart ---
__global__ void k_scan1(int n) {
    __shared__ int sd[256];
    int t = threadIdx.x, i = blockIdx.x * 256 + t;
    int v = (i < n) ? g_cnt[i] : 0;
    sd[t] = v; __syncthreads();
#pragma unroll
    for (int off = 1; off < 256; off <<= 1) {
        int x = (t >= off) ? sd[t - off] : 0;
        __syncthreads();
        sd[t] += x;
        __syncthreads();
    }
    if (i < n) g_rstart[i] = sd[t] - v;
    if (t == 255) g_bsum[blockIdx.x] = sd[255];
}
__global__ void k_scan2(int nb) {
    __shared__ int sd[512];
    int t = threadIdx.x;
    int v = (t < nb) ? g_bsum[t] : 0;
    sd[t] = v; __syncthreads();
#pragma unroll
    for (int off = 1; off < 512; off <<= 1) {
        int x = (t >= off) ? sd[t - off] : 0;
        __syncthreads();
        sd[t] += x;
        __syncthreads();
    }
    if (t < nb) g_bsum[t] = sd[t] - v;
}
__global__ void k_scan3(int n, int E) {
    int i = blockIdx.x * blockDim.x + threadIdx.x;
    if (i < n) {
        int v = g_rstart[i] + g_bsum[i >> 8];
        g_rstart[i] = v;
        g_cursor[i] = v;
    }
    if (i == 0) g_rstart[n] = E;
}
__global__ void k_fill(const int* __restrict__ ei, int E) {
    int e = blockIdx.x * blockDim.x + threadIdx.x;
    if (e >= E) return;
    int pos = atomicAdd(&g_cursor[ei[E + e]], 1);
    g_csre[pos] = e;
}

// ---------------- weight transpose + fp16 round: Wt[n][k] ----------------
__global__ void k_wprep(const float* __restrict__ W, __half* __restrict__ Wt) {
    int i = blockIdx.x * blockDim.x + threadIdx.x;
    if (i >= 512 * 512) return;
    int k = i >> 9, n = i & 511;
    Wt[n * 512 + k] = __float2half_rn(W[i]);
}

// ---------------- activation fp16 cast ----------------
__global__ void k_acast(const float4* __restrict__ X, __half* __restrict__ A, int n4) {
    int i = blockIdx.x * blockDim.x + threadIdx.x;
    if (i >= n4) return;
    float4 v = X[i];
    ((uint2*)A)[i] = make_uint2(
        pack2h(__float2half_rn(v.x), __float2half_rn(v.y)),
        pack2h(__float2half_rn(v.z), __float2half_rn(v.w)));
}

// ---------------- mma.sync fp16 single-pass GEMM, 4-stage pipeline ----------
// C[M,512] = A[M,512] @ W ; A fp16 (rounded), B = Wt[n][k] fp16 (rounded).
// CTA tile 128x128, K step 16, 4-stage cp.async ring, one barrier per step.
// Stage = 2 matrices x 128 rows x 48B pitch = 12KB; 4 stages = 48KB; 2 CTA/SM.
#define PITCH   48
#define MAT_SZ  (128 * PITCH)
#define A_OF 0
#define B_OF (1 * MAT_SZ)
#define STAGE (2 * MAT_SZ)         // 12288
#define NSTG 4
#define GEMM_SMEM (NSTG * STAGE)   // 49152

__global__ __launch_bounds__(256, 2) void gemm_tc(
    const __half* __restrict__ Af, const __half* __restrict__ Bt,
    float* __restrict__ hOut, int M) {
    extern __shared__ char smem[];
    const uint32_t sb = smem_u32(smem);
    const int tid = threadIdx.x, lane = tid & 31, wid = tid >> 5;
    const int bm = blockIdx.x * 128, bn = blockIdx.y * 128;

    const int sr = tid >> 1;
    const bool av = (bm + sr) < M;
    const char* pA = (const char*)Af + ((size_t)(bm + sr) * 512) * 2 + (tid & 1) * 16;
    const char* pB = (const char*)Bt + ((size_t)(bn + sr) * 512) * 2 + (tid & 1) * 16;
    const uint32_t so = (uint32_t)sr * PITCH + (uint32_t)(tid & 1) * 16;

    auto do_stage = [&](int s) {
        const uint32_t bo = sb + (uint32_t)(s & 3) * STAGE;
        const size_t ko = (size_t)s * 32;
        cp16(bo + A_OF + so, pA + ko, av);
        cp16(bo + B_OF + so, pB + ko, true);
        CP_COMMIT();
    };

    const int wm = (wid >> 2) * 64;
    const int wn = (wid & 3) * 32;

    float acc[4][4][4];
#pragma unroll
    for (int i = 0; i < 4; i++)
#pragma unroll
        for (int j = 0; j < 4; j++)
#pragma unroll
            for (int k = 0; k < 4; k++) acc[i][j][k] = 0.0f;

    do_stage(0); do_stage(1); do_stage(2);

#pragma unroll 1
    for (int s = 0; s < 32; ++s) {
        if (s <= 29) CP_WAIT2();
        else if (s == 30) CP_WAIT1();
        else CP_WAIT0();
        __syncthreads();
        if (s + 3 < 32) do_stage(s + 3);

        const uint32_t bufb = sb + (uint32_t)(s & 3) * STAGE;
        uint32_t ah[4][4];
#pragma unroll
        for (int ma = 0; ma < 4; ++ma) {
            uint32_t aaddr = bufb + A_OF +
                (uint32_t)(wm + ma * 16 + (lane & 15)) * PITCH + ((lane >> 4) << 4);
            LDSM_X4(ah[ma], aaddr);
        }
#pragma unroll
        for (int na = 0; na < 4; ++na) {
            uint32_t baddr = bufb + B_OF +
                (uint32_t)(wn + na * 8 + (lane & 7)) * PITCH + (((lane >> 3) & 1) << 4);
            uint32_t bh[2];
            LDSM_X2(bh, baddr);
#pragma unroll
            for (int ma = 0; ma < 4; ++ma)
                mma_f16(acc[ma][na], ah[ma], bh);
        }
    }

#pragma unroll
    for (int ma = 0; ma < 4; ++ma) {
        int r0 = bm + wm + ma * 16 + (lane >> 2);
        int r1 = r0 + 8;
#pragma unroll
        for (int na = 0; na < 4; ++na) {
            int col = bn + wn + na * 8 + 2 * (lane & 3);
            float* c = acc[ma][na];
            if (r0 < M) *(float2*)&hOut[(size_t)r0 * 512 + col] = make_float2(c[0], c[1]);
            if (r1 < M) *(float2*)&hOut[(size_t)r1 * 512 + col] = make_float2(c[2], c[3]);
        }
    }
}

// ---------------- fused gather + epilogue (+ optional cast / projection) ----
// per node: agg = dinv^2*h[node] + sum_in nm*h[row]; bias/relu/L2norm/residual.
// out must NOT alias h; out MAY alias resid (own-row only).
// If af != 0: write fp16 cast of o. If Wf != 0: write p = o @ Wf (512->2).
__global__ __launch_bounds__(128) void k_gather_epi(
    const float* __restrict__ h, const float* __restrict__ bias,
    const float* __restrict__ resid, float* __restrict__ out,
    __half* __restrict__ af, const float* __restrict__ Wf,
    const int* __restrict__ ei, int E, int n) {
    int node = blockIdx.x;
    if (node >= n) return;
    int tid = threadIdx.x;

    float dv = g_dinv[node];
    float d2 = dv * dv;
    const float4* h4 = (const float4*)h;
    float4 v = h4[(size_t)node * 128 + tid];
    float4 acc = make_float4(v.x * d2, v.y * d2, v.z * d2, v.w * d2);

    int beg = g_rstart[node], end = g_rstart[node + 1];
    for (int j = beg; j < end; ++j) {
        int e = g_csre[j];
        float nm = g_enorm[e];
        int r = ei[e];
        float4 hv = h4[(size_t)r * 128 + tid];
        acc.x += nm * hv.x; acc.y += nm * hv.y;
        acc.z += nm * hv.z; acc.w += nm * hv.w;
    }

    float4 b = ((const float4*)bias)[tid];
    acc.x = fmaxf(acc.x + b.x, 0.0f);
    acc.y = fmaxf(acc.y + b.y, 0.0f);
    acc.z = fmaxf(acc.z + b.z, 0.0f);
    acc.w = fmaxf(acc.w + b.w, 0.0f);

    float s = acc.x * acc.x + acc.y * acc.y + acc.z * acc.z + acc.w * acc.w;
#pragma unroll
    for (int off = 16; off > 0; off >>= 1)
        s += __shfl_down_sync(0xFFFFFFFFu, s, off);

    __shared__ float warp_s[4];
    __shared__ float s_total;
    if ((tid & 31) == 0) warp_s[tid >> 5] = s;
    __syncthreads();
    if (tid == 0) s_total = warp_s[0] + warp_s[1] + warp_s[2] + warp_s[3];
    __syncthreads();

    float inv = 0.5f / fmaxf(sqrtf(s_total), 1e-12f);
    float4 r = ((const float4*)(resid + (size_t)node * 512))[tid];
    float4 o = make_float4(acc.x * inv + r.x * 0.5f, acc.y * inv + r.y * 0.5f,
                           acc.z * inv + r.z * 0.5f, acc.w * inv + r.w * 0.5f);
    ((float4*)(out + (size_t)node * 512))[tid] = o;

    if (af) {
        size_t idx = (size_t)node * 128 + tid;
        ((uint2*)af)[idx] = make_uint2(
            pack2h(__float2half_rn(o.x), __float2half_rn(o.y)),
            pack2h(__float2half_rn(o.z), __float2half_rn(o.w)));
    }

    if (Wf) {
        // p[node][j] = sum_k o_k * Wf[k][j], j=0,1 ; Wf row-major [512][2]
        float4 w0 = ((const float4*)Wf)[tid * 2];
        float4 w1 = ((const float4*)Wf)[tid * 2 + 1];
        float s0 = o.x * w0.x + o.y * w0.z + o.z * w1.x + o.w * w1.z;
        float s1 = o.x * w0.y + o.y * w0.w + o.z * w1.y + o.w * w1.w;
#pragma unroll
        for (int off = 16; off > 0; off >>= 1) {
            s0 += __shfl_down_sync(0xFFFFFFFFu, s0, off);
            s1 += __shfl_down_sync(0xFFFFFFFFu, s1, off);
        }
        __shared__ float ws0[4], ws1[4];
        if ((tid & 31) == 0) { ws0[tid >> 5] = s0; ws1[tid >> 5] = s1; }
        __syncthreads();
        if (tid == 0) {
            g_p[node * 2]     = ws0[0] + ws0[1] + ws0[2] + ws0[3];
            g_p[node * 2 + 1] = ws1[0] + ws1[1] + ws1[2] + ws1[3];
        }
    }
}

// fused CSR gather + log_softmax for the 2-wide final conv
__global__ void k_pgather_lsm(const int* __restrict__ ei, const float* __restrict__ bf,
                              int E, int n) {
    int i = blockIdx.x * blockDim.x + threadIdx.x;
    if (i >= n) return;
    float dv = g_dinv[i];
    float d2 = dv * dv;
    float a0 = d2 * g_p[i * 2], a1 = d2 * g_p[i * 2 + 1];
    int beg = g_rstart[i], end = g_rstart[i + 1];
    for (int j = beg; j < end; ++j) {
        int e = g_csre[j];
        float nm = g_enorm[e];
        int r = ei[e];
        a0 += nm * g_p[r * 2];
        a1 += nm * g_p[r * 2 + 1];
    }
    float z0 = a0 + bf[0], z1 = a1 + bf[1];
    float m = fmaxf(z0, z1);
    float lse = m + logf(expf(z0 - m) + expf(z1 - m));
    g_ls[i * 2]     = z0 - lse;
    g_ls[i * 2 + 1] = z1 - lse;
}

__global__ void k_pred(const int* __restrict__ pe, float* __restrict__ out, int NP) {
    int p = blockIdx.x * blockDim.x + threadIdx.x;
    if (p >= NP) return;
    int u = pe[p], v = pe[NP + p];
    out[p * 2]     = -(g_ls[u * 2]     * g_ls[v * 2]);
    out[p * 2 + 1] = -(g_ls[u * 2 + 1] * g_ls[v * 2 + 1]);
}

// ---------------- launch ----------------
extern "C" void kernel_launch(void* const* d_in, const int* in_sizes, int n_in,
                              void* d_out, int out_size) {
    const float* x   = (const float*)d_in[0];
    const int*   ei  = (const int*)d_in[1];
    const float* w   = (const float*)d_in[2];
    const int*   pe  = (const int*)d_in[3];
    const float* W1  = (const float*)d_in[4];
    const float* b1  = (const float*)d_in[5];
    const float* W2  = (const float*)d_in[6];
    const float* b2  = (const float*)d_in[7];
    const float* Wf  = (const float*)d_in[8];
    const float* bf  = (const float*)d_in[9];
    float* out = (float*)d_out;

    const int N  = in_sizes[0] / DDIM;
    const int E  = in_sizes[2];
    const int NP = in_sizes[3] / 2;
    const int NB = (N + 255) / 256;

    float *hbuf, *x1buf;
    __half *af, *w1t, *w2t;
    cudaGetSymbolAddress((void**)&hbuf,  g_h);
    cudaGetSymbolAddress((void**)&x1buf, g_x1);
    cudaGetSymbolAddress((void**)&af,  g_Af);
    cudaGetSymbolAddress((void**)&w1t, g_W1t);
    cudaGetSymbolAddress((void**)&w2t, g_W2t);

    cudaFuncSetAttribute(gemm_tc, cudaFuncAttributeMaxDynamicSharedMemorySize,
                         GEMM_SMEM);

    dim3 ggrid((N + 127) / 128, 4);
    const int n4 = N * (DDIM / 4);

    // precompute: degree/norm + CSR + weight round / act cast
    k_deg_init <<<NB, 256>>>(N);
    k_deg_edges<<<(E + 255) / 256, 256>>>(ei, w, E);
    k_dinv     <<<NB, 256>>>(N);
    k_enorm    <<<(E + 255) / 256, 256>>>(ei, w, E);
    k_scan1    <<<NB, 256>>>(N);
    k_scan2    <<<1, 512>>>(NB);
    k_scan3    <<<NB, 256>>>(N, E);
    k_fill     <<<(E + 255) / 256, 256>>>(ei, E);
    k_wprep    <<<(512 * 512 + 255) / 256, 256>>>(W1, w1t);
    k_wprep    <<<(512 * 512 + 255) / 256, 256>>>(W2, w2t);
    k_acast    <<<(n4 + 255) / 256, 256>>>((const float4*)x, af, n4);

    // ---- layer 1: gemm -> hbuf; gather reads hbuf, writes x1buf + fp16 cast
    gemm_tc     <<<ggrid, 256, GEMM_SMEM>>>(af, w1t, hbuf, N);
    k_gather_epi<<<N, 128>>>(hbuf, b1, x, x1buf, af, (const float*)0, ei, E, N);

    // ---- layer 2: gemm -> hbuf; gather reads hbuf, resid x1buf, writes x1buf
    //      + fused 512->2 projection into g_p
    gemm_tc     <<<ggrid, 256, GEMM_SMEM>>>(af, w2t, hbuf, N);
    k_gather_epi<<<N, 128>>>(hbuf, b2, x1buf, x1buf, (__half*)0, Wf, ei, E, N);

    // ---- final conv scatter + log_softmax ----
    k_pgather_lsm<<<NB, 256>>>(ei, bf, E, N);

    // ---- predictor edges ----
    k_pred<<<(NP + 255) / 256, 256>>>(pe, out, NP);
}

// round 17
// speedup vs baseline: 3.6845x; 1.0361x over previous
#include <cuda_runtime.h>
#include <cuda_fp16.h>
#include <math.h>
#include <stdint.h>

#define NNODES 100000
#define NEDGES 150000
#define NPRED  200000
#define DDIM   512

// ---------------- scratch (no allocs allowed) ----------------
__device__ __half g_Hf [(size_t)NNODES * DDIM];   // GEMM output (fp16)
__device__ float  g_x1 [(size_t)NNODES * DDIM];
__device__ __half g_Af [(size_t)NNODES * DDIM];
__device__ __half g_W1t[512 * 512];
__device__ __half g_W2t[512 * 512];
__device__ float g_deg [NNODES];
__device__ float g_dinv[NNODES];
__device__ float g_enorm[NEDGES];
__device__ float g_p   [NNODES * 2];
__device__ float g_ls  [NNODES * 2];
// CSR (edges grouped by destination col)
__device__ int g_cnt   [NNODES];
__device__ int g_rstart[NNODES + 1];
__device__ int g_cursor[NNODES];
__device__ int g_csre  [NEDGES];
__device__ int g_bsum  [512];

// ---------------- helpers ----------------
__device__ __forceinline__ uint32_t smem_u32(const void* p) {
    uint32_t a;
    asm("{ .reg .u64 t; cvta.to.shared.u64 t, %1; cvt.u32.u64 %0, t; }" : "=r"(a) : "l"(p));
    return a;
}
__device__ __forceinline__ uint32_t pack2h(__half a, __half b) {
    return (uint32_t)__half_as_ushort(a) | ((uint32_t)__half_as_ushort(b) << 16);
}
__device__ __forceinline__ void cp16(uint32_t dst, const void* src, bool p) {
    asm volatile("cp.async.cg.shared.global [%0], [%1], 16, %2;"
                 :: "r"(dst), "l"(src), "r"(p ? 16 : 0) : "memory");
}
#define CP_COMMIT() asm volatile("cp.async.commit_group;" ::: "memory")
#define CP_WAIT2()  asm volatile("cp.async.wait_group 2;" ::: "memory")
#define CP_WAIT1()  asm volatile("cp.async.wait_group 1;" ::: "memory")
#define CP_WAIT0()  asm volatile("cp.async.wait_group 0;" ::: "memory")
#define LDSM_X4(r, a) asm volatile( \
    "ldmatrix.sync.aligned.m8n8.x4.shared.b16 {%0,%1,%2,%3}, [%4];" \
    : "=r"((r)[0]), "=r"((r)[1]), "=r"((r)[2]), "=r"((r)[3]) : "r"(a))
#define LDSM_X2(r, a) asm volatile( \
    "ldmatrix.sync.aligned.m8n8.x2.shared.b16 {%0,%1}, [%2];" \
    : "=r"((r)[0]), "=r"((r)[1]) : "r"(a))

__device__ __forceinline__ void mma_f16(float* c, const uint32_t* a, const uint32_t* b) {
    asm volatile(
        "mma.sync.aligned.m16n8k16.row.col.f32.f16.f16.f32 "
        "{%0,%1,%2,%3}, {%4,%5,%6,%7}, {%8,%9}, {%0,%1,%2,%3};"
        : "+f"(c[0]), "+f"(c[1]), "+f"(c[2]), "+f"(c[3])
        : "r"(a[0]), "r"(a[1]), "r"(a[2]), "r"(a[3]), "r"(b[0]), "r"(b[1]));
}

// ---------------- merged elementwise prep ----------------
// seg 0: deg/cnt init (N); seg 1: wprep W1; seg 2: wprep W2
__global__ void k_prep(const float* __restrict__ W1, const float* __restrict__ W2,
                       int n) {
    int i = blockIdx.x * blockDim.x + threadIdx.x;
    if (i < n) { g_deg[i] = 1.0f; g_cnt[i] = 0; }
    if (i < 512 * 512) {
        int k = i >> 9, c = i & 511;
        g_W1t[c * 512 + k] = __float2half_rn(W1[i]);
        g_W2t[c * 512 + k] = __float2half_rn(W2[i]);
    }
}
__global__ void k_deg_edges(const int* __restrict__ ei, const float* __restrict__ w, int E) {
    int e = blockIdx.x * blockDim.x + threadIdx.x;
    if (e < E) {
        int c = ei[E + e];
        atomicAdd(&g_deg[c], w[e]);
        atomicAdd(&g_cnt[c], 1);
    }
}
__global__ void k_dinv(int n) {
    int i = blockIdx.x * blockDim.x + threadIdx.x;
    if (i < n) {
        float d = g_deg[i];
        g_dinv[i] = (d > 0.0f) ? rsqrtf(fmaxf(d, 1e-12f)) : 0.0f;
    }
}
__global__ void k_enorm(const int* __restrict__ ei, const float* __restrict__ w, int E) {
    int e = blockIdx.x * blockDim.x + threadIdx.x;
    if (e < E) g_enorm[e] = g_dinv[ei[e]] * w[e] * g_dinv[ei[E + e]];
}

// --- 3-kernel exclusive scan of g_cnt -> g_rstart ---
__global__ void k_scan1(int n) {
    __shared__ int sd[256];
    int t = threadIdx.x, i = blockIdx.x * 256 + t;
    int v = (i < n) ? g_cnt[i] : 0;
    sd[t] = v; __syncthreads();
#pragma unroll
    for (int off = 1; off < 256; off <<= 1) {
        int x = (t >= off) ? sd[t - off] : 0;
        __syncthreads();
        sd[t] += x;
        __syncthreads();
    }
    if (i < n) g_rstart[i] = sd[t] - v;
    if (t == 255) g_bsum[blockIdx.x] = sd[255];
}
__global__ void k_scan2(int nb) {
    __shared__ int sd[512];
    int t = threadIdx.x;
    int v = (t < nb) ? g_bsum[t] : 0;
    sd[t] = v; __syncthreads();
#pragma unroll
    for (int off = 1; off < 512; off <<= 1) {
        int x = (t >= off) ? sd[t - off] : 0;
        __syncthreads();
        sd[t] += x;
        __syncthreads();
    }
    if (t < nb) g_bsum[t] = sd[t] - v;
}
__global__ void k_scan3(int n, int E) {
    int i = blockIdx.x * blockDim.x + threadIdx.x;
    if (i < n) {
        int v = g_rstart[i] + g_bsum[i >> 8];
        g_rstart[i] = v;
        g_cursor[i] = v;
    }
    if (i == 0) g_rstart[n] = E;
}
__global__ void k_fill(const int* __restrict__ ei, int E) {
    int e = blockIdx.x * blockDim.x + threadIdx.x;
    if (e >= E) return;
    int pos = atomicAdd(&g_cursor[ei[E + e]], 1);
    g_csre[pos] = e;
}

// ---------------- activation fp16 cast ----------------
__global__ void k_acast(const float4* __restrict__ X, __half* __restrict__ A, int n4) {
    int i = blockIdx.x * blockDim.x + threadIdx.x;
    if (i >= n4) return;
    float4 v = X[i];
    ((uint2*)A)[i] = make_uint2(
        pack2h(__float2half_rn(v.x), __float2half_rn(v.y)),
        pack2h(__float2half_rn(v.z), __float2half_rn(v.w)));
}

// ---------------- mma.sync fp16 single-pass GEMM, 4-stage pipeline ----------
// C[M,512] = A[M,512] @ W ; output stored fp16.
#define PITCH   48
#define MAT_SZ  (128 * PITCH)
#define A_OF 0
#define B_OF (1 * MAT_SZ)
#define STAGE (2 * MAT_SZ)         // 12288
#define NSTG 4
#define GEMM_SMEM (NSTG * STAGE)   // 49152

__global__ __launch_bounds__(256, 2) void gemm_tc(
    const __half* __restrict__ Af, const __half* __restrict__ Bt,
    __half* __restrict__ hOut, int M) {
    extern __shared__ char smem[];
    const uint32_t sb = smem_u32(smem);
    const int tid = threadIdx.x, lane = tid & 31, wid = tid >> 5;
    const int bm = blockIdx.x * 128, bn = blockIdx.y * 128;

    const int sr = tid >> 1;
    const bool av = (bm + sr) < M;
    const char* pA = (const char*)Af + ((size_t)(bm + sr) * 512) * 2 + (tid & 1) * 16;
    const char* pB = (const char*)Bt + ((size_t)(bn + sr) * 512) * 2 + (tid & 1) * 16;
    const uint32_t so = (uint32_t)sr * PITCH + (uint32_t)(tid & 1) * 16;

    auto do_stage = [&](int s) {
        const uint32_t bo = sb + (uint32_t)(s & 3) * STAGE;
        const size_t ko = (size_t)s * 32;
        cp16(bo + A_OF + so, pA + ko, av);
        cp16(bo + B_OF + so, pB + ko, true);
        CP_COMMIT();
    };

    const int wm = (wid >> 2) * 64;
    const int wn = (wid & 3) * 32;

    float acc[4][4][4];
#pragma unroll
    for (int i = 0; i < 4; i++)
#pragma unroll
        for (int j = 0; j < 4; j++)
#pragma unroll
            for (int k = 0; k < 4; k++) acc[i][j][k] = 0.0f;

    do_stage(0); do_stage(1); do_stage(2);

#pragma unroll 1
    for (int s = 0; s < 32; ++s) {
        if (s <= 29) CP_WAIT2();
        else if (s == 30) CP_WAIT1();
        else CP_WAIT0();
        __syncthreads();
        if (s + 3 < 32) do_stage(s + 3);

        const uint32_t bufb = sb + (uint32_t)(s & 3) * STAGE;
        uint32_t ah[4][4];
#pragma unroll
        for (int ma = 0; ma < 4; ++ma) {
            uint32_t aaddr = bufb + A_OF +
                (uint32_t)(wm + ma * 16 + (lane & 15)) * PITCH + ((lane >> 4) << 4);
            LDSM_X4(ah[ma], aaddr);
        }
#pragma unroll
        for (int na = 0; na < 4; ++na) {
            uint32_t baddr = bufb + B_OF +
                (uint32_t)(wn + na * 8 + (lane & 7)) * PITCH + (((lane >> 3) & 1) << 4);
            uint32_t bh[2];
            LDSM_X2(bh, baddr);
#pragma unroll
            for (int ma = 0; ma < 4; ++ma)
                mma_f16(acc[ma][na], ah[ma], bh);
        }
    }

#pragma unroll
    for (int ma = 0; ma < 4; ++ma) {
        int r0 = bm + wm + ma * 16 + (lane >> 2);
        int r1 = r0 + 8;
#pragma unroll
        for (int na = 0; na < 4; ++na) {
            int col = bn + wn + na * 8 + 2 * (lane & 3);
            float* c = acc[ma][na];
            if (r0 < M)
                *(__half2*)&hOut[(size_t)r0 * 512 + col] =
                    __floats2half2_rn(c[0], c[1]);
            if (r1 < M)
                *(__half2*)&hOut[(size_t)r1 * 512 + col] =
                    __floats2half2_rn(c[2], c[3]);
        }
    }
}

// ---------------- fused gather + epilogue (+ optional cast / projection) ----
// per node: agg = dinv^2*h[node] + sum_in nm*h[row] (h fp16);
// then bias/relu/L2norm/residual. out must NOT alias h (different type anyway);
// out MAY alias resid (own-row only).
__global__ __launch_bounds__(128) void k_gather_epi(
    const __half* __restrict__ h, const float* __restrict__ bias,
    const float* __restrict__ resid, float* __restrict__ out,
    __half* __restrict__ af, const float* __restrict__ Wf,
    const int* __restrict__ ei, int E, int n) {
    int node = blockIdx.x;
    if (node >= n) return;
    int tid = threadIdx.x;

    float dv = g_dinv[node];
    float d2 = dv * dv;
    const uint2* h2 = (const uint2*)h;   // 4 halves per uint2; 128 per row

    uint2 hv = h2[(size_t)node * 128 + tid];
    float2 f0 = __half22float2(*(__half2*)&hv.x);
    float2 f1 = __half22float2(*(__half2*)&hv.y);
    float4 acc = make_float4(f0.x * d2, f0.y * d2, f1.x * d2, f1.y * d2);

    int beg = g_rstart[node], end = g_rstart[node + 1];
    for (int j = beg; j < end; ++j) {
        int e = g_csre[j];
        float nm = g_enorm[e];
        int r = ei[e];
        uint2 nv = h2[(size_t)r * 128 + tid];
        float2 n0 = __half22float2(*(__half2*)&nv.x);
        float2 n1 = __half22float2(*(__half2*)&nv.y);
        acc.x += nm * n0.x; acc.y += nm * n0.y;
        acc.z += nm * n1.x; acc.w += nm * n1.y;
    }

    float4 b = ((const float4*)bias)[tid];
    acc.x = fmaxf(acc.x + b.x, 0.0f);
    acc.y = fmaxf(acc.y + b.y, 0.0f);
    acc.z = fmaxf(acc.z + b.z, 0.0f);
    acc.w = fmaxf(acc.w + b.w, 0.0f);

    float s = acc.x * acc.x + acc.y * acc.y + acc.z * acc.z + acc.w * acc.w;
#pragma unroll
    for (int off = 16; off > 0; off >>= 1)
        s += __shfl_down_sync(0xFFFFFFFFu, s, off);

    __shared__ float warp_s[4];
    __shared__ float s_total;
    if ((tid & 31) == 0) warp_s[tid >> 5] = s;
    __syncthreads();
    if (tid == 0) s_total = warp_s[0] + warp_s[1] + warp_s[2] + warp_s[3];
    __syncthreads();

    float inv = 0.5f / fmaxf(sqrtf(s_total), 1e-12f);
    float4 r = ((const float4*)(resid + (size_t)node * 512))[tid];
    float4 o = make_float4(acc.x * inv + r.x * 0.5f, acc.y * inv + r.y * 0.5f,
                           acc.z * inv + r.z * 0.5f, acc.w * inv + r.w * 0.5f);
    ((float4*)(out + (size_t)node * 512))[tid] = o;

    if (af) {
        size_t idx = (size_t)node * 128 + tid;
        ((uint2*)af)[idx] = make_uint2(
            pack2h(__float2half_rn(o.x), __float2half_rn(o.y)),
            pack2h(__float2half_rn(o.z), __float2half_rn(o.w)));
    }

    if (Wf) {
        float4 w0 = ((const float4*)Wf)[tid * 2];
        float4 w1 = ((const float4*)Wf)[tid * 2 + 1];
        float s0 = o.x * w0.x + o.y * w0.z + o.z * w1.x + o.w * w1.z;
        float s1 = o.x * w0.y + o.y * w0.w + o.z * w1.y + o.w * w1.w;
#pragma unroll
        for (int off = 16; off > 0; off >>= 1) {
            s0 += __shfl_down_sync(0xFFFFFFFFu, s0, off);
            s1 += __shfl_down_sync(0xFFFFFFFFu, s1, off);
        }
        __shared__ float ws0[4], ws1[4];
        if ((tid & 31) == 0) { ws0[tid >> 5] = s0; ws1[tid >> 5] = s1; }
        __syncthreads();
        if (tid == 0) {
            g_p[node * 2]     = ws0[0] + ws0[1] + ws0[2] + ws0[3];
            g_p[node * 2 + 1] = ws1[0] + ws1[1] + ws1[2] + ws1[3];
        }
    }
}

// fused CSR gather + log_softmax for the 2-wide final conv
__global__ void k_pgather_lsm(const int* __restrict__ ei, const float* __restrict__ bf,
                              int E, int n) {
    int i = blockIdx.x * blockDim.x + threadIdx.x;
    if (i >= n) return;
    float dv = g_dinv[i];
    float d2 = dv * dv;
    float a0 = d2 * g_p[i * 2], a1 = d2 * g_p[i * 2 + 1];
    int beg = g_rstart[i], end = g_rstart[i + 1];
    for (int j = beg; j < end; ++j) {
        int e = g_csre[j];
        float nm = g_enorm[e];
        int r = ei[e];
        a0 += nm * g_p[r * 2];
        a1 += nm * g_p[r * 2 + 1];
    }
    float z0 = a0 + bf[0], z1 = a1 + bf[1];
    float m = fmaxf(z0, z1);
    float lse = m + logf(expf(z0 - m) + expf(z1 - m));
    g_ls[i * 2]     = z0 - lse;
    g_ls[i * 2 + 1] = z1 - lse;
}

__global__ void k_pred(const int* __restrict__ pe, float* __restrict__ out, int NP) {
    int p = blockIdx.x * blockDim.x + threadIdx.x;
    if (p >= NP) return;
    int u = pe[p], v = pe[NP + p];
    out[p * 2]     = -(g_ls[u * 2]     * g_ls[v * 2]);
    out[p * 2 + 1] = -(g_ls[u * 2 + 1] * g_ls[v * 2 + 1]);
}

// ---------------- launch ----------------
extern "C" void kernel_launch(void* const* d_in, const int* in_sizes, int n_in,
                              void* d_out, int out_size) {
    const float* x   = (const float*)d_in[0];
    const int*   ei  = (const int*)d_in[1];
    const float* w   = (const float*)d_in[2];
    const int*   pe  = (const int*)d_in[3];
    const float* W1  = (const float*)d_in[4];
    const float* b1  = (const float*)d_in[5];
    const float* W2  = (const float*)d_in[6];
    const float* b2  = (const float*)d_in[7];
    const float* Wf  = (const float*)d_in[8];
    const float* bf  = (const float*)d_in[9];
    float* out = (float*)d_out;

    const int N  = in_sizes[0] / DDIM;
    const int E  = in_sizes[2];
    const int NP = in_sizes[3] / 2;
    const int NB = (N + 255) / 256;

    __half *hbuf, *af, *w1t, *w2t;
    float *x1buf;
    cudaGetSymbolAddress((void**)&hbuf,  g_Hf);
    cudaGetSymbolAddress((void**)&x1buf, g_x1);
    cudaGetSymbolAddress((void**)&af,  g_Af);
    cudaGetSymbolAddress((void**)&w1t, g_W1t);
    cudaGetSymbolAddress((void**)&w2t, g_W2t);

    cudaFuncSetAttribute(gemm_tc, cudaFuncAttributeMaxDynamicSharedMemorySize,
                         GEMM_SMEM);

    dim3 ggrid((N + 127) / 128, 4);
    const int n4 = N * (DDIM / 4);
    const int prep_n = (512 * 512 > N) ? 512 * 512 : N;

    // precompute: merged init/wprep + degree/norm + CSR + act cast
    k_prep     <<<(prep_n + 255) / 256, 256>>>(W1, W2, N);
    k_deg_edges<<<(E + 255) / 256, 256>>>(ei, w, E);
    k_dinv     <<<NB, 256>>>(N);
    k_enorm    <<<(E + 255) / 256, 256>>>(ei, w, E);
    k_scan1    <<<NB, 256>>>(N);
    k_scan2    <<<1, 512>>>(NB);
    k_scan3    <<<NB, 256>>>(N, E);
    k_fill     <<<(E + 255) / 256, 256>>>(ei, E);
    k_acast    <<<(n4 + 255) / 256, 256>>>((const float4*)x, af, n4);

    // ---- layer 1: gemm -> hbuf(fp16); gather -> x1buf + fp16 cast into af
    gemm_tc     <<<ggrid, 256, GEMM_SMEM>>>(af, w1t, hbuf, N);
    k_gather_epi<<<N, 128>>>(hbuf, b1, x, x1buf, af, (const float*)0, ei, E, N);

    // ---- layer 2: gemm -> hbuf(fp16); gather -> x1buf + fused 512->2 proj
    gemm_tc     <<<ggrid, 256, GEMM_SMEM>>>(af, w2t, hbuf, N);
    k_gather_epi<<<N, 128>>>(hbuf, b2, x1buf, x1buf, (__half*)0, Wf, ei, E, N);

    // ---- final conv scatter + log_softmax ----
    k_pgather_lsm<<<NB, 256>>>(ei, bf, E, N);

    // ---- predictor edges ----
    k_pred<<<(NP + 255) / 256, 256>>>(pe, out, NP);
}